// round 1
// baseline (speedup 1.0000x reference)
#include <cuda_runtime.h>

#define DIM 16
#define N_ATM 131072
#define N_BND 1048576
#define N_ANG 2097152
#define N_GRAPHS 256
#define PI_F 3.14159265358979323846f

// ---------------- scratch (device globals; BSS zero-init; re-zeroed each launch) ----
__device__ float g_h_atm[N_ATM * DIM];
__device__ float g_h_bnd[N_BND * DIM];
__device__ float g_h_ang[N_ANG * DIM];
__device__ float g_num[N_BND * DIM];    // reused for both graphs (A: bonds, G: atoms)
__device__ float g_den[N_BND * DIM];
__device__ float g_pooled[N_GRAPHS * DIM];

// ---------------- helpers ----------------
__device__ __forceinline__ float sigmoidf_(float x) { return 1.0f / (1.0f + __expf(-x)); }
__device__ __forceinline__ float siluf_(float x)    { return x / (1.0f + __expf(-x)); }

// LayerNorm over the 16-lane group this thread belongs to (lanes 0-15 / 16-31).
__device__ __forceinline__ float ln16(float x, float g, float b) {
    float s = x, q = x * x;
    #pragma unroll
    for (int off = 8; off; off >>= 1) {
        s += __shfl_xor_sync(0xffffffffu, s, off);
        q += __shfl_xor_sync(0xffffffffu, q, off);
    }
    float mu  = s * (1.0f / 16.0f);
    float var = q * (1.0f / 16.0f) - mu * mu;
    return (x - mu) * rsqrtf(var + 1e-5f) * g + b;
}

struct Slot {
    int j, grp, slot, stride;
};
__device__ __forceinline__ Slot make_slot() {
    Slot s;
    int t = blockIdx.x * blockDim.x + threadIdx.x;
    int lane = t & 31;
    s.j = lane & 15;
    s.grp = lane & 16;
    s.slot = ((t >> 5) << 1) + (s.grp >> 4);
    s.stride = ((gridDim.x * blockDim.x) >> 5) << 1;
    return s;
}

// ---------------- encoders ----------------
__global__ void k_enc_atm(const int* __restrict__ xatm,
                          const float* __restrict__ W1, const float* __restrict__ b1,
                          const float* __restrict__ W2, const float* __restrict__ b2,
                          const float* __restrict__ lg, const float* __restrict__ lb) {
    Slot s = make_slot();
    float w2c[16];
    #pragma unroll
    for (int k = 0; k < 16; k++) w2c[k] = W2[k * 16 + s.j];
    float b1j = b1[s.j], b2j = b2[s.j], gj = lg[s.j], bj = lb[s.j];
    for (int a = s.slot; a < N_ATM; a += s.stride) {
        int sp = xatm[a];
        float h = siluf_(W1[sp * 16 + s.j] + b1j);
        float z = b2j;
        #pragma unroll
        for (int k = 0; k < 16; k++)
            z += __shfl_sync(0xffffffffu, h, s.grp | k) * w2c[k];
        g_h_atm[a * 16 + s.j] = ln16(z, gj, bj);
    }
}

__global__ void k_enc_bnd(const float* __restrict__ xb,
                          const float* __restrict__ W1, const float* __restrict__ b1,
                          const float* __restrict__ W2, const float* __restrict__ b2,
                          const float* __restrict__ lg, const float* __restrict__ lb) {
    Slot s = make_slot();
    float w1c[16], w2c[16];
    #pragma unroll
    for (int k = 0; k < 16; k++) { w1c[k] = W1[k * 16 + s.j]; w2c[k] = W2[k * 16 + s.j]; }
    float b1j = b1[s.j], b2j = b2[s.j], gj = lg[s.j], bj = lb[s.j];
    const float nrm = sqrtf(2.0f / 5.0f);
    for (int e = s.slot; e < N_BND; e += s.stride) {
        float xx = xb[e] + 1e-5f;
        float f = nrm * sinf((float)(s.j + 1) * PI_F * xx * (1.0f / 5.0f)) / xx;
        float h = b1j;
        #pragma unroll
        for (int k = 0; k < 16; k++)
            h += __shfl_sync(0xffffffffu, f, s.grp | k) * w1c[k];
        h = siluf_(h);
        float z = b2j;
        #pragma unroll
        for (int k = 0; k < 16; k++)
            z += __shfl_sync(0xffffffffu, h, s.grp | k) * w2c[k];
        g_h_bnd[e * 16 + s.j] = ln16(z, gj, bj);
    }
}

// angle encoder: set 2 (bond-angle, gaussian 0..pi) vs set 3 (dihedral, gaussian -pi..pi)
__global__ void k_enc_ang(const float* __restrict__ xang, const int* __restrict__ mask,
                          const float* __restrict__ W1, const float* __restrict__ b1,
                          const float* __restrict__ W2, const float* __restrict__ b2,
                          const float* __restrict__ lg, const float* __restrict__ lb) {
    Slot s = make_slot();
    float w1b[16], w1d[16], w2b[16], w2d[16];
    #pragma unroll
    for (int k = 0; k < 16; k++) {
        w1b[k] = W1[2 * 256 + k * 16 + s.j];
        w1d[k] = W1[3 * 256 + k * 16 + s.j];
        w2b[k] = W2[2 * 256 + k * 16 + s.j];
        w2d[k] = W2[3 * 256 + k * 16 + s.j];
    }
    float b1b = b1[2 * 16 + s.j], b1d = b1[3 * 16 + s.j];
    float b2b = b2[2 * 16 + s.j], b2d = b2[3 * 16 + s.j];
    float gb_ = lg[2 * 16 + s.j], gd_ = lg[3 * 16 + s.j];
    float bb_ = lb[2 * 16 + s.j], bd_ = lb[3 * 16 + s.j];
    const float cb = (float)s.j * (PI_F / 15.0f);
    const float cd = -PI_F + (float)s.j * (2.0f * PI_F / 15.0f);
    const float gamb = 15.0f / PI_F;
    const float gamd = 7.5f / PI_F;
    for (int e = s.slot; e < N_ANG; e += s.stride) {
        float x = xang[e];
        bool m = mask[e] != 0;
        float tb = gamb * (x - cb), td = gamd * (x - cd);
        float f = m ? __expf(-td * td) : __expf(-tb * tb);
        float h = m ? b1d : b1b;
        #pragma unroll
        for (int k = 0; k < 16; k++) {
            float w = m ? w1d[k] : w1b[k];
            h += __shfl_sync(0xffffffffu, f, s.grp | k) * w;
        }
        h = siluf_(h);
        float z = m ? b2d : b2b;
        #pragma unroll
        for (int k = 0; k < 16; k++) {
            float w = m ? w2d[k] : w2b[k];
            z += __shfl_sync(0xffffffffu, h, s.grp | k) * w;
        }
        g_h_ang[e * 16 + s.j] = ln16(z, m ? gd_ : gb_, m ? bd_ : bb_);
    }
}

// ---------------- edge-gated conv: edge phase ----------------
// which==0: x=g_h_bnd, e=g_h_ang (line graph A). which==1: x=g_h_atm, e=g_h_bnd (graph G).
__global__ void k_conv_edge(int which, const int* __restrict__ src, const int* __restrict__ dst,
                            int E,
                            const float* __restrict__ W, const float* __restrict__ bconv,
                            const float* __restrict__ ln) {
    const float* __restrict__ x = (which == 0) ? g_h_bnd : g_h_atm;
    float* __restrict__ e = (which == 0) ? g_h_ang : g_h_bnd;
    Slot s = make_slot();
    float w0[16], w1[16], w2[16], w4[16];
    #pragma unroll
    for (int k = 0; k < 16; k++) {
        w0[k] = W[0 * 256 + k * 16 + s.j];
        w1[k] = W[1 * 256 + k * 16 + s.j];
        w2[k] = W[2 * 256 + k * 16 + s.j];
        w4[k] = W[4 * 256 + k * 16 + s.j];
    }
    float b0 = bconv[s.j];
    float ge = ln[32 + s.j], be = ln[48 + s.j];
    for (int ed = s.slot; ed < E; ed += s.stride) {
        int si = src[ed], di = dst[ed];
        float xs = x[si * 16 + s.j];
        float xd = x[di * 16 + s.j];
        float ev = e[ed * 16 + s.j];
        float z = b0, mm = 0.0f;
        #pragma unroll
        for (int k = 0; k < 16; k++) {
            float a = __shfl_sync(0xffffffffu, xs, s.grp | k);
            float b = __shfl_sync(0xffffffffu, xd, s.grp | k);
            float c = __shfl_sync(0xffffffffu, ev, s.grp | k);
            z += a * w0[k] + b * w1[k] + c * w2[k];
            mm += a * w4[k];
        }
        float sig = sigmoidf_(z);
        atomicAdd(&g_num[di * 16 + s.j], sig * mm);
        atomicAdd(&g_den[di * 16 + s.j], sig);
        float zl = ln16(z, ge, be);
        e[ed * 16 + s.j] = ev + siluf_(zl);
    }
}

// ---------------- edge-gated conv: node phase (also re-zeros num/den) ----------------
__global__ void k_conv_node(int which,
                            const float* __restrict__ W, const float* __restrict__ bconv,
                            const float* __restrict__ ln) {
    float* __restrict__ x = (which == 0) ? g_h_bnd : g_h_atm;
    int N = (which == 0) ? N_BND : N_ATM;
    Slot s = make_slot();
    float w3[16];
    #pragma unroll
    for (int k = 0; k < 16; k++) w3[k] = W[3 * 256 + k * 16 + s.j];
    float b1 = bconv[16 + s.j];
    float gn = ln[s.j], bn = ln[16 + s.j];
    for (int i = s.slot; i < N; i += s.stride) {
        int idx = i * 16 + s.j;
        float xv = x[idx];
        float u = b1 + g_num[idx] / (g_den[idx] + 1e-5f);
        #pragma unroll
        for (int k = 0; k < 16; k++)
            u += __shfl_sync(0xffffffffu, xv, s.grp | k) * w3[k];
        float ul = ln16(u, gn, bn);
        x[idx] = xv + siluf_(ul);
        g_num[idx] = 0.0f;   // reset scratch for next conv / next replay
        g_den[idx] = 0.0f;
    }
}

// ---------------- pool + head ----------------
__global__ void k_pool(const int* __restrict__ batch) {
    int t = blockIdx.x * blockDim.x + threadIdx.x;
    if (t < N_ATM * 16) {
        int a = t >> 4, j = t & 15;
        atomicAdd(&g_pooled[batch[a] * 16 + j], g_h_atm[t]);
    }
}

__global__ void k_head(const float* __restrict__ fp,
                       const float* __restrict__ l1W, const float* __restrict__ l1b,
                       const float* __restrict__ l2W, const float* __restrict__ l2b,
                       float* __restrict__ out) {
    int g = threadIdx.x;  // one block of 256
    float p[16];
    #pragma unroll
    for (int i = 0; i < 16; i++) p[i] = g_pooled[g * 16 + i];
    float f0 = fp[2 * g], f1 = fp[2 * g + 1];
    float acc = l2b[0];
    #pragma unroll
    for (int jo = 0; jo < 16; jo++) {
        float h = l1b[jo];
        #pragma unroll
        for (int i = 0; i < 16; i++) h += p[i] * l1W[i * 16 + jo];
        h += f0 * l1W[16 * 16 + jo] + f1 * l1W[17 * 16 + jo];
        h = (h > 0.0f) ? h : 0.01f * h;   // leaky_relu(0.01)
        acc += h * l2W[jo];
    }
    out[g] = acc;
    #pragma unroll
    for (int i = 0; i < 16; i++) g_pooled[g * 16 + i] = 0.0f;  // reset for next replay
}

// ---------------- launch ----------------
extern "C" void kernel_launch(void* const* d_in, const int* in_sizes, int n_in,
                              void* d_out, int out_size) {
    const int*   x_atm = (const int*)d_in[0];
    const float* x_bnd = (const float*)d_in[1];
    const float* x_ang = (const float*)d_in[2];
    const int*   mask  = (const int*)d_in[3];
    const int*   eG    = (const int*)d_in[4];   // [2, N_BND]
    const int*   eA    = (const int*)d_in[5];   // [2, N_ANG]
    const int*   batch = (const int*)d_in[6];
    const float* fp    = (const float*)d_in[7];
    const float* W1    = (const float*)d_in[8];
    const float* b1    = (const float*)d_in[9];
    const float* W2    = (const float*)d_in[10];
    const float* b2    = (const float*)d_in[11];
    const float* lg    = (const float*)d_in[12];
    const float* lb    = (const float*)d_in[13];
    const float* cW    = (const float*)d_in[14];  // [3,2,5,16,16]
    const float* cb    = (const float*)d_in[15];  // [3,2,2,16]
    const float* cln   = (const float*)d_in[16];  // [3,2,2,2,16]
    const float* l1W   = (const float*)d_in[17];
    const float* l1b   = (const float*)d_in[18];
    const float* l2W   = (const float*)d_in[19];
    const float* l2b   = (const float*)d_in[20];
    float* out = (float*)d_out;

    k_enc_atm<<<512, 256>>>(x_atm, W1 + 0 * 256, b1 + 0 * 16, W2 + 0 * 256, b2 + 0 * 16,
                            lg + 0 * 16, lb + 0 * 16);
    k_enc_bnd<<<2048, 256>>>(x_bnd, W1 + 1 * 256, b1 + 1 * 16, W2 + 1 * 256, b2 + 1 * 16,
                             lg + 1 * 16, lb + 1 * 16);
    k_enc_ang<<<4096, 256>>>(x_ang, mask, W1, b1, W2, b2, lg, lb);

    for (int c = 0; c < 3; c++) {
        const float* Wa  = cW  + (c * 2 + 0) * 5 * 256;
        const float* ba  = cb  + (c * 2 + 0) * 32;
        const float* lna = cln + (c * 2 + 0) * 64;
        k_conv_edge<<<4096, 256>>>(0, eA, eA + N_ANG, N_ANG, Wa, ba, lna);
        k_conv_node<<<2048, 256>>>(0, Wa, ba, lna);

        const float* Wg  = cW  + (c * 2 + 1) * 5 * 256;
        const float* bg  = cb  + (c * 2 + 1) * 32;
        const float* lng = cln + (c * 2 + 1) * 64;
        k_conv_edge<<<2048, 256>>>(1, eG, eG + N_BND, N_BND, Wg, bg, lng);
        k_conv_node<<<512, 256>>>(1, Wg, bg, lng);
    }

    k_pool<<<8192, 256>>>(batch);
    k_head<<<1, 256>>>(fp, l1W, l1b, l2W, l2b, out);
}

// round 2
// speedup vs baseline: 1.3692x; 1.3692x over previous
#include <cuda_runtime.h>

#define DIM 16
#define N_ATM 131072
#define N_BND 1048576
#define N_ANG 2097152
#define N_GRAPHS 256
#define PI_F 3.14159265358979323846f

// ---------------- scratch (device globals; BSS zero-init; re-zeroed each launch) ----
__device__ float g_h_atm[N_ATM * DIM];
__device__ float g_h_bnd[N_BND * DIM];
__device__ float g_h_ang[N_ANG * DIM];
__device__ float g_num[N_BND * DIM];        // reused for both graphs
__device__ float g_den[N_BND * DIM];
__device__ float g_proj_s[N_BND * 2 * DIM]; // per-node {P0=x@W0+b0, P4=x@W4} interleaved (src gathers)
__device__ float g_proj_d[N_BND * DIM];     // per-node P1=x@W1 (dst gathers)
__device__ float g_pooled[N_GRAPHS * DIM];

// ---------------- helpers ----------------
__device__ __forceinline__ float sigmoidf_(float x) { return 1.0f / (1.0f + __expf(-x)); }
__device__ __forceinline__ float siluf_(float x)    { return x / (1.0f + __expf(-x)); }

// LayerNorm over the 16-lane half-warp group.
__device__ __forceinline__ float ln16(float x, float g, float b) {
    float s = x, q = x * x;
    #pragma unroll
    for (int off = 8; off; off >>= 1) {
        s += __shfl_xor_sync(0xffffffffu, s, off);
        q += __shfl_xor_sync(0xffffffffu, q, off);
    }
    float mu  = s * (1.0f / 16.0f);
    float var = q * (1.0f / 16.0f) - mu * mu;
    return (x - mu) * rsqrtf(var + 1e-5f) * g + b;
}

struct Slot { int j, grp, slot, stride; };
__device__ __forceinline__ Slot make_slot() {
    Slot s;
    int t = blockIdx.x * blockDim.x + threadIdx.x;
    int lane = t & 31;
    s.j = lane & 15;
    s.grp = lane & 16;
    s.slot = ((t >> 5) << 1) + (s.grp >> 4);
    s.stride = ((gridDim.x * blockDim.x) >> 5) << 1;
    return s;
}

// ---------------- encoders ----------------
__global__ void k_enc_atm(const int* __restrict__ xatm,
                          const float* __restrict__ W1, const float* __restrict__ b1,
                          const float* __restrict__ W2, const float* __restrict__ b2,
                          const float* __restrict__ lg, const float* __restrict__ lb) {
    Slot s = make_slot();
    float w2c[16];
    #pragma unroll
    for (int k = 0; k < 16; k++) w2c[k] = W2[k * 16 + s.j];
    float b1j = b1[s.j], b2j = b2[s.j], gj = lg[s.j], bj = lb[s.j];
    for (int a = s.slot; a < N_ATM; a += s.stride) {
        int sp = xatm[a];
        float h = siluf_(W1[sp * 16 + s.j] + b1j);
        float z = b2j;
        #pragma unroll
        for (int k = 0; k < 16; k++)
            z += __shfl_sync(0xffffffffu, h, s.grp | k) * w2c[k];
        g_h_atm[a * 16 + s.j] = ln16(z, gj, bj);
    }
}

__global__ void k_enc_bnd(const float* __restrict__ xb,
                          const float* __restrict__ W1, const float* __restrict__ b1,
                          const float* __restrict__ W2, const float* __restrict__ b2,
                          const float* __restrict__ lg, const float* __restrict__ lb) {
    Slot s = make_slot();
    float w1c[16], w2c[16];
    #pragma unroll
    for (int k = 0; k < 16; k++) { w1c[k] = W1[k * 16 + s.j]; w2c[k] = W2[k * 16 + s.j]; }
    float b1j = b1[s.j], b2j = b2[s.j], gj = lg[s.j], bj = lb[s.j];
    const float nrm = sqrtf(2.0f / 5.0f);
    for (int e = s.slot; e < N_BND; e += s.stride) {
        float xx = xb[e] + 1e-5f;
        float f = nrm * sinf((float)(s.j + 1) * PI_F * xx * (1.0f / 5.0f)) / xx;
        float h = b1j;
        #pragma unroll
        for (int k = 0; k < 16; k++)
            h += __shfl_sync(0xffffffffu, f, s.grp | k) * w1c[k];
        h = siluf_(h);
        float z = b2j;
        #pragma unroll
        for (int k = 0; k < 16; k++)
            z += __shfl_sync(0xffffffffu, h, s.grp | k) * w2c[k];
        g_h_bnd[e * 16 + s.j] = ln16(z, gj, bj);
    }
}

__global__ void k_enc_ang(const float* __restrict__ xang, const int* __restrict__ mask,
                          const float* __restrict__ W1, const float* __restrict__ b1,
                          const float* __restrict__ W2, const float* __restrict__ b2,
                          const float* __restrict__ lg, const float* __restrict__ lb) {
    Slot s = make_slot();
    float w1b[16], w1d[16], w2b[16], w2d[16];
    #pragma unroll
    for (int k = 0; k < 16; k++) {
        w1b[k] = W1[2 * 256 + k * 16 + s.j];
        w1d[k] = W1[3 * 256 + k * 16 + s.j];
        w2b[k] = W2[2 * 256 + k * 16 + s.j];
        w2d[k] = W2[3 * 256 + k * 16 + s.j];
    }
    float b1b = b1[2 * 16 + s.j], b1d = b1[3 * 16 + s.j];
    float b2b = b2[2 * 16 + s.j], b2d = b2[3 * 16 + s.j];
    float gb_ = lg[2 * 16 + s.j], gd_ = lg[3 * 16 + s.j];
    float bb_ = lb[2 * 16 + s.j], bd_ = lb[3 * 16 + s.j];
    const float cb = (float)s.j * (PI_F / 15.0f);
    const float cd = -PI_F + (float)s.j * (2.0f * PI_F / 15.0f);
    const float gamb = 15.0f / PI_F;
    const float gamd = 7.5f / PI_F;
    for (int e = s.slot; e < N_ANG; e += s.stride) {
        float x = xang[e];
        bool m = mask[e] != 0;
        float tb = gamb * (x - cb), td = gamd * (x - cd);
        float f = m ? __expf(-td * td) : __expf(-tb * tb);
        float h = m ? b1d : b1b;
        #pragma unroll
        for (int k = 0; k < 16; k++) {
            float w = m ? w1d[k] : w1b[k];
            h += __shfl_sync(0xffffffffu, f, s.grp | k) * w;
        }
        h = siluf_(h);
        float z = m ? b2d : b2b;
        #pragma unroll
        for (int k = 0; k < 16; k++) {
            float w = m ? w2d[k] : w2b[k];
            z += __shfl_sync(0xffffffffu, h, s.grp | k) * w;
        }
        g_h_ang[e * 16 + s.j] = ln16(z, m ? gd_ : gb_, m ? bd_ : bb_);
    }
}

// ---------------- per-node projections for the edge phase ----------------
// proj_s[i*32 + j]      = (x@W0 + b0)_j
// proj_s[i*32 + 16 + j] = (x@W4)_j
// proj_d[i*16 + j]      = (x@W1)_j
__global__ void k_proj(int which, int N,
                       const float* __restrict__ W, const float* __restrict__ bconv) {
    const float* __restrict__ x = (which == 0) ? g_h_bnd : g_h_atm;
    Slot s = make_slot();
    float w0[16], w1[16], w4[16];
    #pragma unroll
    for (int k = 0; k < 16; k++) {
        w0[k] = W[0 * 256 + k * 16 + s.j];
        w1[k] = W[1 * 256 + k * 16 + s.j];
        w4[k] = W[4 * 256 + k * 16 + s.j];
    }
    float b0 = bconv[s.j];
    for (int i = s.slot; i < N; i += s.stride) {
        float xv = x[i * 16 + s.j];
        float p0 = b0, p1 = 0.0f, p4 = 0.0f;
        #pragma unroll
        for (int k = 0; k < 16; k++) {
            float a = __shfl_sync(0xffffffffu, xv, s.grp | k);
            p0 += a * w0[k];
            p1 += a * w1[k];
            p4 += a * w4[k];
        }
        g_proj_s[i * 32 + s.j]      = p0;
        g_proj_s[i * 32 + 16 + s.j] = p4;
        g_proj_d[i * 16 + s.j]      = p1;
    }
}

// ---------------- edge-gated conv: edge phase (uses precomputed projections) ----
__global__ void __launch_bounds__(256) k_conv_edge(
        int which, const int* __restrict__ src, const int* __restrict__ dst, int E,
        const float* __restrict__ W, const float* __restrict__ ln) {
    float* __restrict__ e = (which == 0) ? g_h_ang : g_h_bnd;
    Slot s = make_slot();
    float w2c[16];
    #pragma unroll
    for (int k = 0; k < 16; k++) w2c[k] = W[2 * 256 + k * 16 + s.j];
    float ge = ln[32 + s.j], be = ln[48 + s.j];
    for (int ed = s.slot; ed < E; ed += s.stride) {
        int si = src[ed], di = dst[ed];
        float p0 = g_proj_s[si * 32 + s.j];
        float p4 = g_proj_s[si * 32 + 16 + s.j];
        float p1 = g_proj_d[di * 16 + s.j];
        float ev = e[ed * 16 + s.j];
        float z = p0 + p1;
        #pragma unroll
        for (int k = 0; k < 16; k++)
            z += __shfl_sync(0xffffffffu, ev, s.grp | k) * w2c[k];
        float sig = sigmoidf_(z);
        atomicAdd(&g_num[di * 16 + s.j], sig * p4);
        atomicAdd(&g_den[di * 16 + s.j], sig);
        e[ed * 16 + s.j] = ev + siluf_(ln16(z, ge, be));
    }
}

// ---------------- edge-gated conv: node phase (also re-zeros num/den) ----------------
__global__ void k_conv_node(int which,
                            const float* __restrict__ W, const float* __restrict__ bconv,
                            const float* __restrict__ ln) {
    float* __restrict__ x = (which == 0) ? g_h_bnd : g_h_atm;
    int N = (which == 0) ? N_BND : N_ATM;
    Slot s = make_slot();
    float w3[16];
    #pragma unroll
    for (int k = 0; k < 16; k++) w3[k] = W[3 * 256 + k * 16 + s.j];
    float b1 = bconv[16 + s.j];
    float gn = ln[s.j], bn = ln[16 + s.j];
    for (int i = s.slot; i < N; i += s.stride) {
        int idx = i * 16 + s.j;
        float xv = x[idx];
        float u = b1 + g_num[idx] / (g_den[idx] + 1e-5f);
        #pragma unroll
        for (int k = 0; k < 16; k++)
            u += __shfl_sync(0xffffffffu, xv, s.grp | k) * w3[k];
        x[idx] = xv + siluf_(ln16(u, gn, bn));
        g_num[idx] = 0.0f;
        g_den[idx] = 0.0f;
    }
}

// ---------------- pool + head ----------------
__global__ void k_pool(const int* __restrict__ batch) {
    int t = blockIdx.x * blockDim.x + threadIdx.x;
    if (t < N_ATM * 16) {
        int a = t >> 4, j = t & 15;
        atomicAdd(&g_pooled[batch[a] * 16 + j], g_h_atm[t]);
    }
}

__global__ void k_head(const float* __restrict__ fp,
                       const float* __restrict__ l1W, const float* __restrict__ l1b,
                       const float* __restrict__ l2W, const float* __restrict__ l2b,
                       float* __restrict__ out) {
    int g = threadIdx.x;  // one block of 256
    float p[16];
    #pragma unroll
    for (int i = 0; i < 16; i++) p[i] = g_pooled[g * 16 + i];
    float f0 = fp[2 * g], f1 = fp[2 * g + 1];
    float acc = l2b[0];
    #pragma unroll
    for (int jo = 0; jo < 16; jo++) {
        float h = l1b[jo];
        #pragma unroll
        for (int i = 0; i < 16; i++) h += p[i] * l1W[i * 16 + jo];
        h += f0 * l1W[16 * 16 + jo] + f1 * l1W[17 * 16 + jo];
        h = (h > 0.0f) ? h : 0.01f * h;
        acc += h * l2W[jo];
    }
    out[g] = acc;
    #pragma unroll
    for (int i = 0; i < 16; i++) g_pooled[g * 16 + i] = 0.0f;
}

// ---------------- launch ----------------
extern "C" void kernel_launch(void* const* d_in, const int* in_sizes, int n_in,
                              void* d_out, int out_size) {
    const int*   x_atm = (const int*)d_in[0];
    const float* x_bnd = (const float*)d_in[1];
    const float* x_ang = (const float*)d_in[2];
    const int*   mask  = (const int*)d_in[3];
    const int*   eG    = (const int*)d_in[4];
    const int*   eA    = (const int*)d_in[5];
    const int*   batch = (const int*)d_in[6];
    const float* fp    = (const float*)d_in[7];
    const float* W1    = (const float*)d_in[8];
    const float* b1    = (const float*)d_in[9];
    const float* W2    = (const float*)d_in[10];
    const float* b2    = (const float*)d_in[11];
    const float* lg    = (const float*)d_in[12];
    const float* lb    = (const float*)d_in[13];
    const float* cW    = (const float*)d_in[14];
    const float* cb    = (const float*)d_in[15];
    const float* cln   = (const float*)d_in[16];
    const float* l1W   = (const float*)d_in[17];
    const float* l1b   = (const float*)d_in[18];
    const float* l2W   = (const float*)d_in[19];
    const float* l2b   = (const float*)d_in[20];
    float* out = (float*)d_out;

    k_enc_atm<<<512, 256>>>(x_atm, W1 + 0 * 256, b1 + 0 * 16, W2 + 0 * 256, b2 + 0 * 16,
                            lg + 0 * 16, lb + 0 * 16);
    k_enc_bnd<<<2048, 256>>>(x_bnd, W1 + 1 * 256, b1 + 1 * 16, W2 + 1 * 256, b2 + 1 * 16,
                             lg + 1 * 16, lb + 1 * 16);
    k_enc_ang<<<4096, 256>>>(x_ang, mask, W1, b1, W2, b2, lg, lb);

    for (int c = 0; c < 3; c++) {
        const float* Wa  = cW  + (c * 2 + 0) * 5 * 256;
        const float* ba  = cb  + (c * 2 + 0) * 32;
        const float* lna = cln + (c * 2 + 0) * 64;
        k_proj<<<2048, 256>>>(0, N_BND, Wa, ba);
        k_conv_edge<<<8192, 256>>>(0, eA, eA + N_ANG, N_ANG, Wa, lna);
        k_conv_node<<<2048, 256>>>(0, Wa, ba, lna);

        const float* Wg  = cW  + (c * 2 + 1) * 5 * 256;
        const float* bg  = cb  + (c * 2 + 1) * 32;
        const float* lng = cln + (c * 2 + 1) * 64;
        k_proj<<<512, 256>>>(1, N_ATM, Wg, bg);
        k_conv_edge<<<4096, 256>>>(1, eG, eG + N_BND, N_BND, Wg, lng);
        k_conv_node<<<512, 256>>>(1, Wg, bg, lng);
    }

    k_pool<<<8192, 256>>>(batch);
    k_head<<<1, 256>>>(fp, l1W, l1b, l2W, l2b, out);
}

// round 3
// speedup vs baseline: 1.5119x; 1.1042x over previous
#include <cuda_runtime.h>

#define DIM 16
#define N_ATM 131072
#define N_BND 1048576
#define N_ANG 2097152
#define N_GRAPHS 256
#define PI_F 3.14159265358979323846f

// ---------------- scratch (device globals; zero-init; invariants restored each replay) ----
__device__ float g_h_atm[N_ATM * DIM];
__device__ float g_h_bnd[N_BND * DIM];
__device__ float g_h_ang[N_ANG * DIM];
__device__ float g_acc[N_BND * 2 * DIM];   // interleaved (num_j, den_j) pairs; bonds or atoms
__device__ float g_bps[N_BND * 2 * DIM];   // bond src-proj interleaved (p0_j, p4_j)
__device__ float g_bpd[N_BND * DIM];       // bond dst-proj p1
__device__ float g_aps[N_ATM * 2 * DIM];   // atom src-proj interleaved (p0_j, p4_j)
__device__ float g_apd[N_ATM * DIM];       // atom dst-proj p1
__device__ float g_pooled[N_GRAPHS * DIM];

// ---------------- helpers ----------------
__device__ __forceinline__ float sigmoidf_(float x) { return 1.0f / (1.0f + __expf(-x)); }
__device__ __forceinline__ float siluf_(float x)    { return x / (1.0f + __expf(-x)); }

__device__ __forceinline__ float ln16(float x, float g, float b) {
    float s = x, q = x * x;
    #pragma unroll
    for (int off = 8; off; off >>= 1) {
        s += __shfl_xor_sync(0xffffffffu, s, off);
        q += __shfl_xor_sync(0xffffffffu, q, off);
    }
    float mu  = s * (1.0f / 16.0f);
    float var = q * (1.0f / 16.0f) - mu * mu;
    return (x - mu) * rsqrtf(var + 1e-5f) * g + b;
}

struct Slot { int j, grp, slot, stride; };
__device__ __forceinline__ Slot make_slot() {
    Slot s;
    int t = blockIdx.x * blockDim.x + threadIdx.x;
    int lane = t & 31;
    s.j = lane & 15;
    s.grp = lane & 16;
    s.slot = ((t >> 5) << 1) + (s.grp >> 4);
    s.stride = ((gridDim.x * blockDim.x) >> 5) << 1;
    return s;
}

// paired vector reduction: lanes exchange with neighbor, even lanes issue RED.128
__device__ __forceinline__ void red_pair(float* base, int node, int j, float a, float b) {
    float a1 = __shfl_xor_sync(0xffffffffu, a, 1);
    float b1 = __shfl_xor_sync(0xffffffffu, b, 1);
    if ((j & 1) == 0) {
        float* p = base + (size_t)node * 32 + 2 * j;
        asm volatile("red.global.add.v4.f32 [%0], {%1, %2, %3, %4};"
                     :: "l"(p), "f"(a), "f"(b), "f"(a1), "f"(b1) : "memory");
    }
}

// smem weight pack for fused projection: [0,256)=W0, [256,512)=W1, [512,768)=W4, [768,784)=b0
__device__ __forceinline__ void load_wproj(float* sw, const float* W, const float* b) {
    for (int i = threadIdx.x; i < 784; i += blockDim.x) {
        if (i < 768) {
            int m = i >> 8;
            int mm = (m == 2) ? 4 : m;
            sw[i] = W[mm * 256 + (i & 255)];
        } else {
            sw[i] = b[i - 768];
        }
    }
    __syncthreads();
}

// project register value v (per-lane channel) through smem weights; store to node arrays
__device__ __forceinline__ void proj_store(float v, const Slot& s, const float* sw,
                                           float* dst_s, float* dst_d, int i) {
    float p0 = sw[768 + s.j], p1 = 0.0f, p4 = 0.0f;
    #pragma unroll
    for (int k = 0; k < 16; k++) {
        float a = __shfl_sync(0xffffffffu, v, s.grp | k);
        p0 += a * sw[k * 16 + s.j];
        p1 += a * sw[256 + k * 16 + s.j];
        p4 += a * sw[512 + k * 16 + s.j];
    }
    *(float2*)(dst_s + (size_t)i * 32 + 2 * s.j) = make_float2(p0, p4);
    dst_d[(size_t)i * 16 + s.j] = p1;
}

// ---------------- encoders (fused with first-conv projections) ----------------
__global__ void __launch_bounds__(256) k_enc_atm(
        const int* __restrict__ xatm,
        const float* __restrict__ W1, const float* __restrict__ b1,
        const float* __restrict__ W2, const float* __restrict__ b2,
        const float* __restrict__ lg, const float* __restrict__ lb,
        const float* __restrict__ Wg0, const float* __restrict__ bg0) {
    __shared__ float sw[784];
    load_wproj(sw, Wg0, bg0);
    Slot s = make_slot();
    float w2c[16];
    #pragma unroll
    for (int k = 0; k < 16; k++) w2c[k] = W2[k * 16 + s.j];
    float b1j = b1[s.j], b2j = b2[s.j], gj = lg[s.j], bj = lb[s.j];
    for (int a = s.slot; a < N_ATM; a += s.stride) {
        int sp = xatm[a];
        float h = siluf_(W1[sp * 16 + s.j] + b1j);
        float z = b2j;
        #pragma unroll
        for (int k = 0; k < 16; k++)
            z += __shfl_sync(0xffffffffu, h, s.grp | k) * w2c[k];
        float v = ln16(z, gj, bj);
        g_h_atm[a * 16 + s.j] = v;
        proj_store(v, s, sw, g_aps, g_apd, a);
    }
}

__global__ void __launch_bounds__(256) k_enc_bnd(
        const float* __restrict__ xb,
        const float* __restrict__ W1, const float* __restrict__ b1,
        const float* __restrict__ W2, const float* __restrict__ b2,
        const float* __restrict__ lg, const float* __restrict__ lb,
        const float* __restrict__ Wa0, const float* __restrict__ ba0) {
    __shared__ float sw[784];
    load_wproj(sw, Wa0, ba0);
    Slot s = make_slot();
    float w1c[16], w2c[16];
    #pragma unroll
    for (int k = 0; k < 16; k++) { w1c[k] = W1[k * 16 + s.j]; w2c[k] = W2[k * 16 + s.j]; }
    float b1j = b1[s.j], b2j = b2[s.j], gj = lg[s.j], bj = lb[s.j];
    const float nrm = sqrtf(2.0f / 5.0f);
    for (int e = s.slot; e < N_BND; e += s.stride) {
        float xx = xb[e] + 1e-5f;
        float f = nrm * sinf((float)(s.j + 1) * PI_F * xx * (1.0f / 5.0f)) / xx;
        float h = b1j;
        #pragma unroll
        for (int k = 0; k < 16; k++)
            h += __shfl_sync(0xffffffffu, f, s.grp | k) * w1c[k];
        h = siluf_(h);
        float z = b2j;
        #pragma unroll
        for (int k = 0; k < 16; k++)
            z += __shfl_sync(0xffffffffu, h, s.grp | k) * w2c[k];
        float v = ln16(z, gj, bj);
        g_h_bnd[e * 16 + s.j] = v;
        proj_store(v, s, sw, g_bps, g_bpd, e);
    }
}

__global__ void __launch_bounds__(256) k_enc_ang(
        const float* __restrict__ xang, const int* __restrict__ mask,
        const float* __restrict__ W1, const float* __restrict__ b1,
        const float* __restrict__ W2, const float* __restrict__ b2,
        const float* __restrict__ lg, const float* __restrict__ lb) {
    Slot s = make_slot();
    float w1b[16], w1d[16], w2b[16], w2d[16];
    #pragma unroll
    for (int k = 0; k < 16; k++) {
        w1b[k] = W1[2 * 256 + k * 16 + s.j];
        w1d[k] = W1[3 * 256 + k * 16 + s.j];
        w2b[k] = W2[2 * 256 + k * 16 + s.j];
        w2d[k] = W2[3 * 256 + k * 16 + s.j];
    }
    float b1b = b1[2 * 16 + s.j], b1d = b1[3 * 16 + s.j];
    float b2b = b2[2 * 16 + s.j], b2d = b2[3 * 16 + s.j];
    float gb_ = lg[2 * 16 + s.j], gd_ = lg[3 * 16 + s.j];
    float bb_ = lb[2 * 16 + s.j], bd_ = lb[3 * 16 + s.j];
    const float cb = (float)s.j * (PI_F / 15.0f);
    const float cd = -PI_F + (float)s.j * (2.0f * PI_F / 15.0f);
    const float gamb = 15.0f / PI_F;
    const float gamd = 7.5f / PI_F;
    for (int e = s.slot; e < N_ANG; e += s.stride) {
        float x = xang[e];
        bool m = mask[e] != 0;
        float tb = gamb * (x - cb), td = gamd * (x - cd);
        float f = m ? __expf(-td * td) : __expf(-tb * tb);
        float h = m ? b1d : b1b;
        #pragma unroll
        for (int k = 0; k < 16; k++) {
            float w = m ? w1d[k] : w1b[k];
            h += __shfl_sync(0xffffffffu, f, s.grp | k) * w;
        }
        h = siluf_(h);
        float z = m ? b2d : b2b;
        #pragma unroll
        for (int k = 0; k < 16; k++) {
            float w = m ? w2d[k] : w2b[k];
            z += __shfl_sync(0xffffffffu, h, s.grp | k) * w;
        }
        g_h_ang[e * 16 + s.j] = ln16(z, m ? gd_ : gb_, m ? bd_ : bb_);
    }
}

// ---------------- A-graph edge phase (bonds -> angles) ----------------
__global__ void __launch_bounds__(256) k_edge_A(
        const int* __restrict__ src, const int* __restrict__ dst,
        const float* __restrict__ W, const float* __restrict__ ln) {
    Slot s = make_slot();
    float w2c[16];
    #pragma unroll
    for (int k = 0; k < 16; k++) w2c[k] = W[2 * 256 + k * 16 + s.j];
    float ge = ln[32 + s.j], be = ln[48 + s.j];
    for (int ed = s.slot; ed < N_ANG; ed += s.stride) {
        int si = src[ed], di = dst[ed];
        float2 pv = *(const float2*)(g_bps + (size_t)si * 32 + 2 * s.j);  // (p0, p4)
        float p1 = g_bpd[(size_t)di * 16 + s.j];
        float ev = g_h_ang[(size_t)ed * 16 + s.j];
        float z = pv.x + p1;
        #pragma unroll
        for (int k = 0; k < 16; k++)
            z += __shfl_sync(0xffffffffu, ev, s.grp | k) * w2c[k];
        float sig = sigmoidf_(z);
        red_pair(g_acc, di, s.j, sig * pv.y, sig);
        g_h_ang[(size_t)ed * 16 + s.j] = ev + siluf_(ln16(z, ge, be));
    }
}

// ---------------- A-graph node phase (update bonds; zero acc) ----------------
__global__ void __launch_bounds__(256) k_node_A(
        const float* __restrict__ W, const float* __restrict__ bconv,
        const float* __restrict__ ln) {
    Slot s = make_slot();
    float w3[16];
    #pragma unroll
    for (int k = 0; k < 16; k++) w3[k] = W[3 * 256 + k * 16 + s.j];
    float b1 = bconv[16 + s.j];
    float gn = ln[s.j], bn = ln[16 + s.j];
    for (int i = s.slot; i < N_BND; i += s.stride) {
        float2 nd = *(const float2*)(g_acc + (size_t)i * 32 + 2 * s.j);
        float xv = g_h_bnd[(size_t)i * 16 + s.j];
        float u = b1 + nd.x / (nd.y + 1e-5f);
        #pragma unroll
        for (int k = 0; k < 16; k++)
            u += __shfl_sync(0xffffffffu, xv, s.grp | k) * w3[k];
        g_h_bnd[(size_t)i * 16 + s.j] = xv + siluf_(ln16(u, gn, bn));
        *(float2*)(g_acc + (size_t)i * 32 + 2 * s.j) = make_float2(0.0f, 0.0f);
    }
}

// ---------------- G-graph edge phase (atoms -> bonds), fused next-A bond proj ----
__global__ void __launch_bounds__(256) k_edge_G(
        const int* __restrict__ src, const int* __restrict__ dst,
        const float* __restrict__ W, const float* __restrict__ ln,
        const float* __restrict__ Wnext, const float* __restrict__ bnext) {
    __shared__ float sw[784];
    bool has_next = (Wnext != nullptr);
    if (has_next) load_wproj(sw, Wnext, bnext);
    Slot s = make_slot();
    float w2c[16];
    #pragma unroll
    for (int k = 0; k < 16; k++) w2c[k] = W[2 * 256 + k * 16 + s.j];
    float ge = ln[32 + s.j], be = ln[48 + s.j];
    for (int ed = s.slot; ed < N_BND; ed += s.stride) {
        int si = src[ed], di = dst[ed];
        float2 pv = *(const float2*)(g_aps + (size_t)si * 32 + 2 * s.j);
        float p1 = g_apd[(size_t)di * 16 + s.j];
        float ev = g_h_bnd[(size_t)ed * 16 + s.j];
        float z = pv.x + p1;
        #pragma unroll
        for (int k = 0; k < 16; k++)
            z += __shfl_sync(0xffffffffu, ev, s.grp | k) * w2c[k];
        float sig = sigmoidf_(z);
        red_pair(g_acc, di, s.j, sig * pv.y, sig);
        float en = ev + siluf_(ln16(z, ge, be));
        g_h_bnd[(size_t)ed * 16 + s.j] = en;
        if (has_next) proj_store(en, s, sw, g_bps, g_bpd, ed);
    }
}

// ---------------- G-graph node phase (update atoms; zero acc; next-G proj; pool) ----
__global__ void __launch_bounds__(256) k_node_G(
        const float* __restrict__ W, const float* __restrict__ bconv,
        const float* __restrict__ ln,
        const float* __restrict__ Wnext, const float* __restrict__ bnext,
        const int* __restrict__ batch, int is_last) {
    __shared__ float sw[784];
    bool has_next = (Wnext != nullptr);
    if (has_next) load_wproj(sw, Wnext, bnext);
    Slot s = make_slot();
    float w3[16];
    #pragma unroll
    for (int k = 0; k < 16; k++) w3[k] = W[3 * 256 + k * 16 + s.j];
    float b1 = bconv[16 + s.j];
    float gn = ln[s.j], bn = ln[16 + s.j];
    for (int i = s.slot; i < N_ATM; i += s.stride) {
        float2 nd = *(const float2*)(g_acc + (size_t)i * 32 + 2 * s.j);
        float xv = g_h_atm[(size_t)i * 16 + s.j];
        float u = b1 + nd.x / (nd.y + 1e-5f);
        #pragma unroll
        for (int k = 0; k < 16; k++)
            u += __shfl_sync(0xffffffffu, xv, s.grp | k) * w3[k];
        float xn = xv + siluf_(ln16(u, gn, bn));
        g_h_atm[(size_t)i * 16 + s.j] = xn;
        *(float2*)(g_acc + (size_t)i * 32 + 2 * s.j) = make_float2(0.0f, 0.0f);
        if (has_next) proj_store(xn, s, sw, g_aps, g_apd, i);
        if (is_last) atomicAdd(&g_pooled[batch[i] * 16 + s.j], xn);
    }
}

// ---------------- head (also re-zeroes pooled for next replay) ----------------
__global__ void k_head(const float* __restrict__ fp,
                       const float* __restrict__ l1W, const float* __restrict__ l1b,
                       const float* __restrict__ l2W, const float* __restrict__ l2b,
                       float* __restrict__ out) {
    int g = threadIdx.x;  // one block of 256
    float p[16];
    #pragma unroll
    for (int i = 0; i < 16; i++) p[i] = g_pooled[g * 16 + i];
    float f0 = fp[2 * g], f1 = fp[2 * g + 1];
    float acc = l2b[0];
    #pragma unroll
    for (int jo = 0; jo < 16; jo++) {
        float h = l1b[jo];
        #pragma unroll
        for (int i = 0; i < 16; i++) h += p[i] * l1W[i * 16 + jo];
        h += f0 * l1W[16 * 16 + jo] + f1 * l1W[17 * 16 + jo];
        h = (h > 0.0f) ? h : 0.01f * h;
        acc += h * l2W[jo];
    }
    out[g] = acc;
    #pragma unroll
    for (int i = 0; i < 16; i++) g_pooled[g * 16 + i] = 0.0f;
}

// ---------------- launch ----------------
extern "C" void kernel_launch(void* const* d_in, const int* in_sizes, int n_in,
                              void* d_out, int out_size) {
    const int*   x_atm = (const int*)d_in[0];
    const float* x_bnd = (const float*)d_in[1];
    const float* x_ang = (const float*)d_in[2];
    const int*   mask  = (const int*)d_in[3];
    const int*   eG    = (const int*)d_in[4];
    const int*   eA    = (const int*)d_in[5];
    const int*   batch = (const int*)d_in[6];
    const float* fp    = (const float*)d_in[7];
    const float* W1    = (const float*)d_in[8];
    const float* b1    = (const float*)d_in[9];
    const float* W2    = (const float*)d_in[10];
    const float* b2    = (const float*)d_in[11];
    const float* lg    = (const float*)d_in[12];
    const float* lb    = (const float*)d_in[13];
    const float* cW    = (const float*)d_in[14];  // [3,2,5,16,16]
    const float* cb    = (const float*)d_in[15];  // [3,2,2,16]
    const float* cln   = (const float*)d_in[16];  // [3,2,2,2,16]
    const float* l1W   = (const float*)d_in[17];
    const float* l1b   = (const float*)d_in[18];
    const float* l2W   = (const float*)d_in[19];
    const float* l2b   = (const float*)d_in[20];
    float* out = (float*)d_out;

    #define WA(c)  (cW  + ((c) * 2 + 0) * 5 * 256)
    #define BA(c)  (cb  + ((c) * 2 + 0) * 32)
    #define LNA(c) (cln + ((c) * 2 + 0) * 64)
    #define WG(c)  (cW  + ((c) * 2 + 1) * 5 * 256)
    #define BG(c)  (cb  + ((c) * 2 + 1) * 32)
    #define LNG(c) (cln + ((c) * 2 + 1) * 64)

    k_enc_atm<<<512, 256>>>(x_atm, W1 + 0 * 256, b1 + 0 * 16, W2 + 0 * 256, b2 + 0 * 16,
                            lg + 0 * 16, lb + 0 * 16, WG(0), BG(0));
    k_enc_bnd<<<2048, 256>>>(x_bnd, W1 + 1 * 256, b1 + 1 * 16, W2 + 1 * 256, b2 + 1 * 16,
                             lg + 1 * 16, lb + 1 * 16, WA(0), BA(0));
    k_enc_ang<<<8192, 256>>>(x_ang, mask, W1, b1, W2, b2, lg, lb);

    for (int c = 0; c < 3; c++) {
        k_edge_A<<<8192, 256>>>(eA, eA + N_ANG, WA(c), LNA(c));
        k_node_A<<<2048, 256>>>(WA(c), BA(c), LNA(c));

        const float* WnA = (c < 2) ? WA(c + 1) : nullptr;
        const float* bnA = (c < 2) ? BA(c + 1) : nullptr;
        k_edge_G<<<4096, 256>>>(eG, eG + N_BND, WG(c), LNG(c), WnA, bnA);

        const float* WnG = (c < 2) ? WG(c + 1) : nullptr;
        const float* bnG = (c < 2) ? BG(c + 1) : nullptr;
        k_node_G<<<512, 256>>>(WG(c), BG(c), LNG(c), WnG, bnG, batch, (c == 2) ? 1 : 0);
    }

    k_head<<<1, 256>>>(fp, l1W, l1b, l2W, l2b, out);
}

// round 4
// speedup vs baseline: 1.6218x; 1.0726x over previous
#include <cuda_runtime.h>
#include <cuda_fp16.h>

#define DIM 16
#define N_ATM 131072
#define N_BND 1048576
#define N_ANG 2097152
#define N_GRAPHS 256
#define PI_F 3.14159265358979323846f

// ---------------- scratch (device globals; zero-init; invariants restored each replay) ----
__device__ float  g_h_atm[N_ATM * DIM];
__device__ float  g_h_bnd[N_BND * DIM];
__device__ __half g_h_ang[N_ANG * DIM];    // fp16 storage (post-LN, O(1) values)
__device__ float  g_acc[N_BND * 2 * DIM];  // interleaved (num_j, den_j) pairs
__device__ float  g_bps[N_BND * 2 * DIM];  // bond src-proj interleaved (p0_j, p4_j)
__device__ float  g_bpd[N_BND * DIM];      // bond dst-proj p1
__device__ float  g_aps[N_ATM * 2 * DIM];  // atom src-proj interleaved (p0_j, p4_j)
__device__ float  g_apd[N_ATM * DIM];      // atom dst-proj p1
__device__ float  g_pooled[N_GRAPHS * DIM];

// ---------------- helpers ----------------
__device__ __forceinline__ float sigmoidf_(float x) { return 1.0f / (1.0f + __expf(-x)); }
__device__ __forceinline__ float siluf_(float x)    { return x / (1.0f + __expf(-x)); }

__device__ __forceinline__ float ln16(float x, float g, float b) {
    float s = x, q = x * x;
    #pragma unroll
    for (int off = 8; off; off >>= 1) {
        s += __shfl_xor_sync(0xffffffffu, s, off);
        q += __shfl_xor_sync(0xffffffffu, q, off);
    }
    float mu  = s * (1.0f / 16.0f);
    float var = q * (1.0f / 16.0f) - mu * mu;
    return (x - mu) * rsqrtf(var + 1e-5f) * g + b;
}

struct Slot { int j, grp, slot, stride; };
__device__ __forceinline__ Slot make_slot() {
    Slot s;
    int t = blockIdx.x * blockDim.x + threadIdx.x;
    int lane = t & 31;
    s.j = lane & 15;
    s.grp = lane & 16;
    s.slot = ((t >> 5) << 1) + (s.grp >> 4);
    s.stride = ((gridDim.x * blockDim.x) >> 5) << 1;
    return s;
}

// paired vector reduction: lanes exchange with neighbor, even lanes issue RED.128
__device__ __forceinline__ void red_pair(float* base, int node, int j, float a, float b) {
    float a1 = __shfl_xor_sync(0xffffffffu, a, 1);
    float b1 = __shfl_xor_sync(0xffffffffu, b, 1);
    if ((j & 1) == 0) {
        float* p = base + (size_t)node * 32 + 2 * j;
        asm volatile("red.global.add.v4.f32 [%0], {%1, %2, %3, %4};"
                     :: "l"(p), "f"(a), "f"(b), "f"(a1), "f"(b1) : "memory");
    }
}

// smem weight pack for fused projection: [0,256)=W0, [256,512)=W1, [512,768)=W4, [768,784)=b0
__device__ __forceinline__ void load_wproj(float* sw, const float* W, const float* b) {
    for (int i = threadIdx.x; i < 784; i += blockDim.x) {
        if (i < 768) {
            int m = i >> 8;
            int mm = (m == 2) ? 4 : m;
            sw[i] = W[mm * 256 + (i & 255)];
        } else {
            sw[i] = b[i - 768];
        }
    }
    __syncthreads();
}

// project register value v through smem weights; store to node arrays
__device__ __forceinline__ void proj_store(float v, const Slot& s, const float* sw,
                                           float* dst_s, float* dst_d, int i) {
    float p0 = sw[768 + s.j], p1 = 0.0f, p4 = 0.0f;
    #pragma unroll
    for (int k = 0; k < 16; k++) {
        float a = __shfl_sync(0xffffffffu, v, s.grp | k);
        p0 += a * sw[k * 16 + s.j];
        p1 += a * sw[256 + k * 16 + s.j];
        p4 += a * sw[512 + k * 16 + s.j];
    }
    *(float2*)(dst_s + (size_t)i * 32 + 2 * s.j) = make_float2(p0, p4);
    dst_d[(size_t)i * 16 + s.j] = p1;
}

// shared edge-A body once ev (angle feature) is known
__device__ __forceinline__ void edgeA_core(int ed, int si, int di, float ev,
                                           const float* w2c, float ge, float be,
                                           const Slot& s, bool write_e) {
    float2 pv = *(const float2*)(g_bps + (size_t)si * 32 + 2 * s.j);  // (p0, p4)
    float p1 = g_bpd[(size_t)di * 16 + s.j];
    float z = pv.x + p1;
    #pragma unroll
    for (int k = 0; k < 16; k++)
        z += __shfl_sync(0xffffffffu, ev, s.grp | k) * w2c[k];
    float sig = sigmoidf_(z);
    red_pair(g_acc, di, s.j, sig * pv.y, sig);
    if (write_e)
        g_h_ang[(size_t)ed * 16 + s.j] = __float2half_rn(ev + siluf_(ln16(z, ge, be)));
}

// ---------------- encoders (fused with first-conv projections) ----------------
__global__ void __launch_bounds__(256) k_enc_atm(
        const int* __restrict__ xatm,
        const float* __restrict__ W1, const float* __restrict__ b1,
        const float* __restrict__ W2, const float* __restrict__ b2,
        const float* __restrict__ lg, const float* __restrict__ lb,
        const float* __restrict__ Wg0, const float* __restrict__ bg0) {
    __shared__ float sw[784];
    load_wproj(sw, Wg0, bg0);
    Slot s = make_slot();
    float w2c[16];
    #pragma unroll
    for (int k = 0; k < 16; k++) w2c[k] = W2[k * 16 + s.j];
    float b1j = b1[s.j], b2j = b2[s.j], gj = lg[s.j], bj = lb[s.j];
    for (int a = s.slot; a < N_ATM; a += s.stride) {
        int sp = xatm[a];
        float h = siluf_(W1[sp * 16 + s.j] + b1j);
        float z = b2j;
        #pragma unroll
        for (int k = 0; k < 16; k++)
            z += __shfl_sync(0xffffffffu, h, s.grp | k) * w2c[k];
        float v = ln16(z, gj, bj);
        g_h_atm[a * 16 + s.j] = v;
        proj_store(v, s, sw, g_aps, g_apd, a);
    }
}

__global__ void __launch_bounds__(256) k_enc_bnd(
        const float* __restrict__ xb,
        const float* __restrict__ W1, const float* __restrict__ b1,
        const float* __restrict__ W2, const float* __restrict__ b2,
        const float* __restrict__ lg, const float* __restrict__ lb,
        const float* __restrict__ Wa0, const float* __restrict__ ba0) {
    __shared__ float sw[784];
    load_wproj(sw, Wa0, ba0);
    Slot s = make_slot();
    float w1c[16], w2c[16];
    #pragma unroll
    for (int k = 0; k < 16; k++) { w1c[k] = W1[k * 16 + s.j]; w2c[k] = W2[k * 16 + s.j]; }
    float b1j = b1[s.j], b2j = b2[s.j], gj = lg[s.j], bj = lb[s.j];
    const float nrm = sqrtf(2.0f / 5.0f);
    for (int e = s.slot; e < N_BND; e += s.stride) {
        float xx = xb[e] + 1e-5f;
        float f = nrm * sinf((float)(s.j + 1) * PI_F * xx * (1.0f / 5.0f)) / xx;
        float h = b1j;
        #pragma unroll
        for (int k = 0; k < 16; k++)
            h += __shfl_sync(0xffffffffu, f, s.grp | k) * w1c[k];
        h = siluf_(h);
        float z = b2j;
        #pragma unroll
        for (int k = 0; k < 16; k++)
            z += __shfl_sync(0xffffffffu, h, s.grp | k) * w2c[k];
        float v = ln16(z, gj, bj);
        g_h_bnd[e * 16 + s.j] = v;
        proj_store(v, s, sw, g_bps, g_bpd, e);
    }
}

// ---------------- A-graph edge phase, conv 0: fused angle encoder ----------------
// smem: [0,256)=W1b, [256,512)=W1d, [512,768)=W2b, [768,1024)=W2d,
//       [1024,1152): b1b,b1d,b2b,b2d,gb,gd,lbb,lbd (8x16)
__global__ void __launch_bounds__(256) k_edge_A_first(
        const int* __restrict__ src, const int* __restrict__ dst,
        const float* __restrict__ xang, const int* __restrict__ mask,
        const float* __restrict__ W1, const float* __restrict__ b1,
        const float* __restrict__ W2, const float* __restrict__ b2,
        const float* __restrict__ lg, const float* __restrict__ lb,
        const float* __restrict__ W, const float* __restrict__ ln) {
    __shared__ float sw[1152];
    for (int i = threadIdx.x; i < 1152; i += blockDim.x) {
        if (i < 512)       sw[i] = W1[512 + i];           // sets 2,3 of W1
        else if (i < 1024) sw[i] = W2[i];                 // 512+(i-512): sets 2,3 of W2
        else {
            int idx = i - 1024, gsel = idx >> 4, j = idx & 15;
            const float* tbl[8] = { b1 + 32, b1 + 48, b2 + 32, b2 + 48,
                                    lg + 32, lg + 48, lb + 32, lb + 48 };
            sw[i] = tbl[gsel][j];
        }
    }
    __syncthreads();
    Slot s = make_slot();
    float w2c[16];
    #pragma unroll
    for (int k = 0; k < 16; k++) w2c[k] = W[2 * 256 + k * 16 + s.j];
    float ge = ln[32 + s.j], be = ln[48 + s.j];
    const float cb = (float)s.j * (PI_F / 15.0f);
    const float cd = -PI_F + (float)s.j * (2.0f * PI_F / 15.0f);
    const float* sv = sw + 1024;
    for (int ed = s.slot; ed < N_ANG; ed += s.stride) {
        int si = src[ed], di = dst[ed];
        float x = xang[ed];
        bool m = mask[ed] != 0;
        int o = m ? 256 : 0, o16 = m ? 16 : 0;
        float gam = m ? (7.5f / PI_F) : (15.0f / PI_F);
        float t = gam * (x - (m ? cd : cb));
        float f = __expf(-t * t);
        const float* w1p = sw + o;
        const float* w2p = sw + 512 + o;
        float h = sv[o16 + s.j];
        #pragma unroll
        for (int k = 0; k < 16; k++)
            h += __shfl_sync(0xffffffffu, f, s.grp | k) * w1p[k * 16 + s.j];
        h = siluf_(h);
        float z2 = sv[32 + o16 + s.j];
        #pragma unroll
        for (int k = 0; k < 16; k++)
            z2 += __shfl_sync(0xffffffffu, h, s.grp | k) * w2p[k * 16 + s.j];
        float ev = ln16(z2, sv[64 + o16 + s.j], sv[96 + o16 + s.j]);
        edgeA_core(ed, si, di, ev, w2c, ge, be, s, true);
    }
}

// ---------------- A-graph edge phase, conv 1/2 ----------------
__global__ void __launch_bounds__(256) k_edge_A(
        const int* __restrict__ src, const int* __restrict__ dst,
        const float* __restrict__ W, const float* __restrict__ ln, int write_e) {
    Slot s = make_slot();
    float w2c[16];
    #pragma unroll
    for (int k = 0; k < 16; k++) w2c[k] = W[2 * 256 + k * 16 + s.j];
    float ge = ln[32 + s.j], be = ln[48 + s.j];
    for (int ed = s.slot; ed < N_ANG; ed += s.stride) {
        int si = src[ed], di = dst[ed];
        float ev = __half2float(g_h_ang[(size_t)ed * 16 + s.j]);
        edgeA_core(ed, si, di, ev, w2c, ge, be, s, write_e != 0);
    }
}

// ---------------- A-graph node phase (update bonds; zero acc) ----------------
__global__ void __launch_bounds__(256) k_node_A(
        const float* __restrict__ W, const float* __restrict__ bconv,
        const float* __restrict__ ln) {
    Slot s = make_slot();
    float w3[16];
    #pragma unroll
    for (int k = 0; k < 16; k++) w3[k] = W[3 * 256 + k * 16 + s.j];
    float b1 = bconv[16 + s.j];
    float gn = ln[s.j], bn = ln[16 + s.j];
    for (int i = s.slot; i < N_BND; i += s.stride) {
        float2 nd = *(const float2*)(g_acc + (size_t)i * 32 + 2 * s.j);
        float xv = g_h_bnd[(size_t)i * 16 + s.j];
        float u = b1 + nd.x / (nd.y + 1e-5f);
        #pragma unroll
        for (int k = 0; k < 16; k++)
            u += __shfl_sync(0xffffffffu, xv, s.grp | k) * w3[k];
        g_h_bnd[(size_t)i * 16 + s.j] = xv + siluf_(ln16(u, gn, bn));
        *(float2*)(g_acc + (size_t)i * 32 + 2 * s.j) = make_float2(0.0f, 0.0f);
    }
}

// ---------------- G-graph edge phase (atoms -> bonds), fused next-A bond proj ----
__global__ void __launch_bounds__(256) k_edge_G(
        const int* __restrict__ src, const int* __restrict__ dst,
        const float* __restrict__ W, const float* __restrict__ ln,
        const float* __restrict__ Wnext, const float* __restrict__ bnext) {
    __shared__ float sw[784];
    bool has_next = (Wnext != nullptr);
    if (has_next) load_wproj(sw, Wnext, bnext);
    Slot s = make_slot();
    float w2c[16];
    #pragma unroll
    for (int k = 0; k < 16; k++) w2c[k] = W[2 * 256 + k * 16 + s.j];
    float ge = ln[32 + s.j], be = ln[48 + s.j];
    for (int ed = s.slot; ed < N_BND; ed += s.stride) {
        int si = src[ed], di = dst[ed];
        float2 pv = *(const float2*)(g_aps + (size_t)si * 32 + 2 * s.j);
        float p1 = g_apd[(size_t)di * 16 + s.j];
        float ev = g_h_bnd[(size_t)ed * 16 + s.j];
        float z = pv.x + p1;
        #pragma unroll
        for (int k = 0; k < 16; k++)
            z += __shfl_sync(0xffffffffu, ev, s.grp | k) * w2c[k];
        float sig = sigmoidf_(z);
        red_pair(g_acc, di, s.j, sig * pv.y, sig);
        if (has_next) {
            float en = ev + siluf_(ln16(z, ge, be));
            g_h_bnd[(size_t)ed * 16 + s.j] = en;
            proj_store(en, s, sw, g_bps, g_bpd, ed);
        }
    }
}

// ---------------- G-graph node phase (update atoms; zero acc; next-G proj; pool) ----
__global__ void __launch_bounds__(256) k_node_G(
        const float* __restrict__ W, const float* __restrict__ bconv,
        const float* __restrict__ ln,
        const float* __restrict__ Wnext, const float* __restrict__ bnext,
        const int* __restrict__ batch, int is_last) {
    __shared__ float sw[784];
    bool has_next = (Wnext != nullptr);
    if (has_next) load_wproj(sw, Wnext, bnext);
    Slot s = make_slot();
    float w3[16];
    #pragma unroll
    for (int k = 0; k < 16; k++) w3[k] = W[3 * 256 + k * 16 + s.j];
    float b1 = bconv[16 + s.j];
    float gn = ln[s.j], bn = ln[16 + s.j];
    for (int i = s.slot; i < N_ATM; i += s.stride) {
        float2 nd = *(const float2*)(g_acc + (size_t)i * 32 + 2 * s.j);
        float xv = g_h_atm[(size_t)i * 16 + s.j];
        float u = b1 + nd.x / (nd.y + 1e-5f);
        #pragma unroll
        for (int k = 0; k < 16; k++)
            u += __shfl_sync(0xffffffffu, xv, s.grp | k) * w3[k];
        float xn = xv + siluf_(ln16(u, gn, bn));
        *(float2*)(g_acc + (size_t)i * 32 + 2 * s.j) = make_float2(0.0f, 0.0f);
        if (is_last) {
            atomicAdd(&g_pooled[batch[i] * 16 + s.j], xn);
        } else {
            g_h_atm[(size_t)i * 16 + s.j] = xn;
            proj_store(xn, s, sw, g_aps, g_apd, i);
        }
    }
}

// ---------------- head (also re-zeroes pooled for next replay) ----------------
__global__ void k_head(const float* __restrict__ fp,
                       const float* __restrict__ l1W, const float* __restrict__ l1b,
                       const float* __restrict__ l2W, const float* __restrict__ l2b,
                       float* __restrict__ out) {
    int g = threadIdx.x;  // one block of 256
    float p[16];
    #pragma unroll
    for (int i = 0; i < 16; i++) p[i] = g_pooled[g * 16 + i];
    float f0 = fp[2 * g], f1 = fp[2 * g + 1];
    float acc = l2b[0];
    #pragma unroll
    for (int jo = 0; jo < 16; jo++) {
        float h = l1b[jo];
        #pragma unroll
        for (int i = 0; i < 16; i++) h += p[i] * l1W[i * 16 + jo];
        h += f0 * l1W[16 * 16 + jo] + f1 * l1W[17 * 16 + jo];
        h = (h > 0.0f) ? h : 0.01f * h;
        acc += h * l2W[jo];
    }
    out[g] = acc;
    #pragma unroll
    for (int i = 0; i < 16; i++) g_pooled[g * 16 + i] = 0.0f;
}

// ---------------- launch ----------------
extern "C" void kernel_launch(void* const* d_in, const int* in_sizes, int n_in,
                              void* d_out, int out_size) {
    const int*   x_atm = (const int*)d_in[0];
    const float* x_bnd = (const float*)d_in[1];
    const float* x_ang = (const float*)d_in[2];
    const int*   mask  = (const int*)d_in[3];
    const int*   eG    = (const int*)d_in[4];
    const int*   eA    = (const int*)d_in[5];
    const int*   batch = (const int*)d_in[6];
    const float* fp    = (const float*)d_in[7];
    const float* W1    = (const float*)d_in[8];
    const float* b1    = (const float*)d_in[9];
    const float* W2    = (const float*)d_in[10];
    const float* b2    = (const float*)d_in[11];
    const float* lg    = (const float*)d_in[12];
    const float* lb    = (const float*)d_in[13];
    const float* cW    = (const float*)d_in[14];  // [3,2,5,16,16]
    const float* cb    = (const float*)d_in[15];  // [3,2,2,16]
    const float* cln   = (const float*)d_in[16];  // [3,2,2,2,16]
    const float* l1W   = (const float*)d_in[17];
    const float* l1b   = (const float*)d_in[18];
    const float* l2W   = (const float*)d_in[19];
    const float* l2b   = (const float*)d_in[20];
    float* out = (float*)d_out;

    #define WA(c)  (cW  + ((c) * 2 + 0) * 5 * 256)
    #define BA(c)  (cb  + ((c) * 2 + 0) * 32)
    #define LNA(c) (cln + ((c) * 2 + 0) * 64)
    #define WG(c)  (cW  + ((c) * 2 + 1) * 5 * 256)
    #define BG(c)  (cb  + ((c) * 2 + 1) * 32)
    #define LNG(c) (cln + ((c) * 2 + 1) * 64)

    k_enc_atm<<<512, 256>>>(x_atm, W1 + 0 * 256, b1 + 0 * 16, W2 + 0 * 256, b2 + 0 * 16,
                            lg + 0 * 16, lb + 0 * 16, WG(0), BG(0));
    k_enc_bnd<<<2048, 256>>>(x_bnd, W1 + 1 * 256, b1 + 1 * 16, W2 + 1 * 256, b2 + 1 * 16,
                             lg + 1 * 16, lb + 1 * 16, WA(0), BA(0));

    for (int c = 0; c < 3; c++) {
        if (c == 0) {
            k_edge_A_first<<<8192, 256>>>(eA, eA + N_ANG, x_ang, mask,
                                          W1, b1, W2, b2, lg, lb, WA(0), LNA(0));
        } else {
            k_edge_A<<<8192, 256>>>(eA, eA + N_ANG, WA(c), LNA(c), (c < 2) ? 1 : 0);
        }
        k_node_A<<<2048, 256>>>(WA(c), BA(c), LNA(c));

        const float* WnA = (c < 2) ? WA(c + 1) : nullptr;
        const float* bnA = (c < 2) ? BA(c + 1) : nullptr;
        k_edge_G<<<4096, 256>>>(eG, eG + N_BND, WG(c), LNG(c), WnA, bnA);

        const float* WnG = (c < 2) ? WG(c + 1) : nullptr;
        const float* bnG = (c < 2) ? BG(c + 1) : nullptr;
        k_node_G<<<512, 256>>>(WG(c), BG(c), LNG(c), WnG, bnG, batch, (c == 2) ? 1 : 0);
    }

    k_head<<<1, 256>>>(fp, l1W, l1b, l2W, l2b, out);
}

// round 5
// speedup vs baseline: 1.7182x; 1.0595x over previous
#include <cuda_runtime.h>
#include <cuda_fp16.h>

#define DIM 16
#define N_ATM 131072
#define N_BND 1048576
#define N_ANG 2097152
#define N_GRAPHS 256
#define PI_F 3.14159265358979323846f

// ---------------- scratch (device globals; zero-init; invariants restored each replay) ----
__device__ float  g_h_atm[N_ATM * DIM];
__device__ float  g_h_bnd[N_BND * DIM];
__device__ __half g_h_ang[N_ANG * DIM];     // fp16 storage (post-LN, O(1) values)
__device__ float  g_accA[N_BND * 2 * DIM];  // bond (num,den) pairs, zeroed by edge_G
__device__ float  g_accG[N_ATM * 2 * DIM];  // atom (num,den) pairs, zeroed by node_G
__device__ float  g_bps[N_BND * 2 * DIM];   // bond src-proj interleaved (p0_j, p4_j)
__device__ float  g_bpd[N_BND * DIM];       // bond dst-proj p1
__device__ float  g_aps[N_ATM * 2 * DIM];   // atom src-proj interleaved (p0_j, p4_j)
__device__ float  g_apd[N_ATM * DIM];       // atom dst-proj p1
__device__ float  g_pooled[N_GRAPHS * DIM];

// ---------------- helpers ----------------
__device__ __forceinline__ float sigmoidf_(float x) { return 1.0f / (1.0f + __expf(-x)); }
__device__ __forceinline__ float siluf_(float x)    { return x / (1.0f + __expf(-x)); }

__device__ __forceinline__ float ln16(float x, float g, float b) {
    float s = x, q = x * x;
    #pragma unroll
    for (int off = 8; off; off >>= 1) {
        s += __shfl_xor_sync(0xffffffffu, s, off);
        q += __shfl_xor_sync(0xffffffffu, q, off);
    }
    float mu  = s * (1.0f / 16.0f);
    float var = q * (1.0f / 16.0f) - mu * mu;
    return (x - mu) * rsqrtf(var + 1e-5f) * g + b;
}

struct Slot { int j, grp, slot, stride; };
__device__ __forceinline__ Slot make_slot() {
    Slot s;
    int t = blockIdx.x * blockDim.x + threadIdx.x;
    int lane = t & 31;
    s.j = lane & 15;
    s.grp = lane & 16;
    s.slot = ((t >> 5) << 1) + (s.grp >> 4);
    s.stride = ((gridDim.x * blockDim.x) >> 5) << 1;
    return s;
}

// paired vector reduction: lanes exchange with neighbor, even lanes issue RED.128
__device__ __forceinline__ void red_pair(float* base, int node, int j, float a, float b) {
    float a1 = __shfl_xor_sync(0xffffffffu, a, 1);
    float b1 = __shfl_xor_sync(0xffffffffu, b, 1);
    if ((j & 1) == 0) {
        float* p = base + (size_t)node * 32 + 2 * j;
        asm volatile("red.global.add.v4.f32 [%0], {%1, %2, %3, %4};"
                     :: "l"(p), "f"(a), "f"(b), "f"(a1), "f"(b1) : "memory");
    }
}

// smem weight pack for fused projection: [0,256)=W0, [256,512)=W1, [512,768)=W4, [768,784)=b0
__device__ __forceinline__ void load_wproj(float* sw, const float* W, const float* b) {
    for (int i = threadIdx.x; i < 784; i += blockDim.x) {
        if (i < 768) {
            int m = i >> 8;
            int mm = (m == 2) ? 4 : m;
            sw[i] = W[mm * 256 + (i & 255)];
        } else {
            sw[i] = b[i - 768];
        }
    }
    __syncthreads();
}

// project register value v through smem weights; store to node arrays
__device__ __forceinline__ void proj_store(float v, const Slot& s, const float* sw,
                                           float* dst_s, float* dst_d, int i) {
    float p0 = sw[768 + s.j], p1 = 0.0f, p4 = 0.0f;
    #pragma unroll
    for (int k = 0; k < 16; k++) {
        float a = __shfl_sync(0xffffffffu, v, s.grp | k);
        p0 += a * sw[k * 16 + s.j];
        p1 += a * sw[256 + k * 16 + s.j];
        p4 += a * sw[512 + k * 16 + s.j];
    }
    *(float2*)(dst_s + (size_t)i * 32 + 2 * s.j) = make_float2(p0, p4);
    dst_d[(size_t)i * 16 + s.j] = p1;
}

// shared edge-A body once ev (angle feature) is known
__device__ __forceinline__ void edgeA_core(int ed, int si, int di, float ev,
                                           const float* w2c, float ge, float be,
                                           const Slot& s, bool write_e) {
    float2 pv = *(const float2*)(g_bps + (size_t)si * 32 + 2 * s.j);  // (p0, p4)
    float p1 = g_bpd[(size_t)di * 16 + s.j];
    float z = pv.x + p1;
    #pragma unroll
    for (int k = 0; k < 16; k++)
        z += __shfl_sync(0xffffffffu, ev, s.grp | k) * w2c[k];
    float sig = sigmoidf_(z);
    red_pair(g_accA, di, s.j, sig * pv.y, sig);
    if (write_e)
        g_h_ang[(size_t)ed * 16 + s.j] = __float2half_rn(ev + siluf_(ln16(z, ge, be)));
}

// ---------------- encoders (fused with first-conv projections) ----------------
__global__ void __launch_bounds__(256) k_enc_atm(
        const int* __restrict__ xatm,
        const float* __restrict__ W1, const float* __restrict__ b1,
        const float* __restrict__ W2, const float* __restrict__ b2,
        const float* __restrict__ lg, const float* __restrict__ lb,
        const float* __restrict__ Wg0, const float* __restrict__ bg0) {
    __shared__ float sw[784];
    load_wproj(sw, Wg0, bg0);
    Slot s = make_slot();
    float w2c[16];
    #pragma unroll
    for (int k = 0; k < 16; k++) w2c[k] = W2[k * 16 + s.j];
    float b1j = b1[s.j], b2j = b2[s.j], gj = lg[s.j], bj = lb[s.j];
    for (int a = s.slot; a < N_ATM; a += s.stride) {
        int sp = xatm[a];
        float h = siluf_(W1[sp * 16 + s.j] + b1j);
        float z = b2j;
        #pragma unroll
        for (int k = 0; k < 16; k++)
            z += __shfl_sync(0xffffffffu, h, s.grp | k) * w2c[k];
        float v = ln16(z, gj, bj);
        g_h_atm[a * 16 + s.j] = v;
        proj_store(v, s, sw, g_aps, g_apd, a);
    }
}

__global__ void __launch_bounds__(256) k_enc_bnd(
        const float* __restrict__ xb,
        const float* __restrict__ W1, const float* __restrict__ b1,
        const float* __restrict__ W2, const float* __restrict__ b2,
        const float* __restrict__ lg, const float* __restrict__ lb,
        const float* __restrict__ Wa0, const float* __restrict__ ba0) {
    __shared__ float sw[784];
    load_wproj(sw, Wa0, ba0);
    Slot s = make_slot();
    float w1c[16], w2c[16];
    #pragma unroll
    for (int k = 0; k < 16; k++) { w1c[k] = W1[k * 16 + s.j]; w2c[k] = W2[k * 16 + s.j]; }
    float b1j = b1[s.j], b2j = b2[s.j], gj = lg[s.j], bj = lb[s.j];
    const float nrm = sqrtf(2.0f / 5.0f);
    for (int e = s.slot; e < N_BND; e += s.stride) {
        float xx = xb[e] + 1e-5f;
        float f = nrm * sinf((float)(s.j + 1) * PI_F * xx * (1.0f / 5.0f)) / xx;
        float h = b1j;
        #pragma unroll
        for (int k = 0; k < 16; k++)
            h += __shfl_sync(0xffffffffu, f, s.grp | k) * w1c[k];
        h = siluf_(h);
        float z = b2j;
        #pragma unroll
        for (int k = 0; k < 16; k++)
            z += __shfl_sync(0xffffffffu, h, s.grp | k) * w2c[k];
        float v = ln16(z, gj, bj);
        g_h_bnd[e * 16 + s.j] = v;
        proj_store(v, s, sw, g_bps, g_bpd, e);
    }
}

// ---------------- A-graph edge phase, conv 0: fused angle encoder ----------------
__global__ void __launch_bounds__(256) k_edge_A_first(
        const int* __restrict__ src, const int* __restrict__ dst,
        const float* __restrict__ xang, const int* __restrict__ mask,
        const float* __restrict__ W1, const float* __restrict__ b1,
        const float* __restrict__ W2, const float* __restrict__ b2,
        const float* __restrict__ lg, const float* __restrict__ lb,
        const float* __restrict__ W, const float* __restrict__ ln) {
    __shared__ float sw[1152];
    for (int i = threadIdx.x; i < 1152; i += blockDim.x) {
        if (i < 512)       sw[i] = W1[512 + i];           // sets 2,3 of W1
        else if (i < 1024) sw[i] = W2[i];                 // sets 2,3 of W2
        else {
            int idx = i - 1024, gsel = idx >> 4, j = idx & 15;
            const float* tbl[8] = { b1 + 32, b1 + 48, b2 + 32, b2 + 48,
                                    lg + 32, lg + 48, lb + 32, lb + 48 };
            sw[i] = tbl[gsel][j];
        }
    }
    __syncthreads();
    Slot s = make_slot();
    float w2c[16];
    #pragma unroll
    for (int k = 0; k < 16; k++) w2c[k] = W[2 * 256 + k * 16 + s.j];
    float ge = ln[32 + s.j], be = ln[48 + s.j];
    const float cb = (float)s.j * (PI_F / 15.0f);
    const float cd = -PI_F + (float)s.j * (2.0f * PI_F / 15.0f);
    const float* sv = sw + 1024;
    for (int ed = s.slot; ed < N_ANG; ed += s.stride) {
        int si = src[ed], di = dst[ed];
        float x = xang[ed];
        bool m = mask[ed] != 0;
        int o = m ? 256 : 0, o16 = m ? 16 : 0;
        float gam = m ? (7.5f / PI_F) : (15.0f / PI_F);
        float t = gam * (x - (m ? cd : cb));
        float f = __expf(-t * t);
        const float* w1p = sw + o;
        const float* w2p = sw + 512 + o;
        float h = sv[o16 + s.j];
        #pragma unroll
        for (int k = 0; k < 16; k++)
            h += __shfl_sync(0xffffffffu, f, s.grp | k) * w1p[k * 16 + s.j];
        h = siluf_(h);
        float z2 = sv[32 + o16 + s.j];
        #pragma unroll
        for (int k = 0; k < 16; k++)
            z2 += __shfl_sync(0xffffffffu, h, s.grp | k) * w2p[k * 16 + s.j];
        float ev = ln16(z2, sv[64 + o16 + s.j], sv[96 + o16 + s.j]);
        edgeA_core(ed, si, di, ev, w2c, ge, be, s, true);
    }
}

// ---------------- A-graph edge phase, conv 1/2 ----------------
__global__ void __launch_bounds__(256) k_edge_A(
        const int* __restrict__ src, const int* __restrict__ dst,
        const float* __restrict__ W, const float* __restrict__ ln, int write_e) {
    Slot s = make_slot();
    float w2c[16];
    #pragma unroll
    for (int k = 0; k < 16; k++) w2c[k] = W[2 * 256 + k * 16 + s.j];
    float ge = ln[32 + s.j], be = ln[48 + s.j];
    for (int ed = s.slot; ed < N_ANG; ed += s.stride) {
        int si = src[ed], di = dst[ed];
        float ev = __half2float(g_h_ang[(size_t)ed * 16 + s.j]);
        edgeA_core(ed, si, di, ev, w2c, ge, be, s, write_e != 0);
    }
}

// ---------------- G-graph edge phase with FUSED A-node update ----------------
// For G-edge ed (== bond id): finish the A-conv bond update from g_accA, use the
// result as the edge feature, RED into g_accG, optionally store e_new + next-A proj.
// smem: [0,784) next-A proj pack; [784,1040) W3_A; [1040,1056) b1_A;
//       [1056,1072) gn_A; [1072,1088) bn_A
__global__ void __launch_bounds__(256) k_edge_G(
        const int* __restrict__ src, const int* __restrict__ dst,
        const float* __restrict__ Wg, const float* __restrict__ lnG,
        const float* __restrict__ Wa, const float* __restrict__ ba,
        const float* __restrict__ lnA,
        const float* __restrict__ Wnext, const float* __restrict__ bnext) {
    __shared__ float sw[1088];
    bool has_next = (Wnext != nullptr);
    for (int i = threadIdx.x; i < 1088; i += blockDim.x) {
        if (i < 784) {
            if (has_next) {
                if (i < 768) {
                    int m = i >> 8;
                    int mm = (m == 2) ? 4 : m;
                    sw[i] = Wnext[mm * 256 + (i & 255)];
                } else sw[i] = bnext[i - 768];
            }
        }
        else if (i < 1040) sw[i] = Wa[3 * 256 + (i - 784)];
        else if (i < 1056) sw[i] = ba[16 + (i - 1040)];
        else if (i < 1072) sw[i] = lnA[i - 1056];
        else               sw[i] = lnA[16 + (i - 1072)];
    }
    __syncthreads();
    Slot s = make_slot();
    float w2c[16];
    #pragma unroll
    for (int k = 0; k < 16; k++) w2c[k] = Wg[2 * 256 + k * 16 + s.j];
    float ge = lnG[32 + s.j], be = lnG[48 + s.j];
    float b1A = sw[1040 + s.j], gnA = sw[1056 + s.j], bnA = sw[1072 + s.j];
    for (int ed = s.slot; ed < N_BND; ed += s.stride) {
        int si = src[ed], di = dst[ed];
        // --- fused A-node update for bond ed ---
        float2 nd = *(const float2*)(g_accA + (size_t)ed * 32 + 2 * s.j);
        float xv = g_h_bnd[(size_t)ed * 16 + s.j];
        float u = b1A + nd.x / (nd.y + 1e-5f);
        #pragma unroll
        for (int k = 0; k < 16; k++)
            u += __shfl_sync(0xffffffffu, xv, s.grp | k) * sw[784 + k * 16 + s.j];
        float ev = xv + siluf_(ln16(u, gnA, bnA));
        *(float2*)(g_accA + (size_t)ed * 32 + 2 * s.j) = make_float2(0.0f, 0.0f);
        // --- G edge ---
        float2 pv = *(const float2*)(g_aps + (size_t)si * 32 + 2 * s.j);
        float p1 = g_apd[(size_t)di * 16 + s.j];
        float z = pv.x + p1;
        #pragma unroll
        for (int k = 0; k < 16; k++)
            z += __shfl_sync(0xffffffffu, ev, s.grp | k) * w2c[k];
        float sig = sigmoidf_(z);
        red_pair(g_accG, di, s.j, sig * pv.y, sig);
        if (has_next) {
            float en = ev + siluf_(ln16(z, ge, be));
            g_h_bnd[(size_t)ed * 16 + s.j] = en;
            proj_store(en, s, sw, g_bps, g_bpd, ed);
        }
    }
}

// ---------------- G-graph node phase (update atoms; zero accG; next-G proj; pool) ----
__global__ void __launch_bounds__(256) k_node_G(
        const float* __restrict__ W, const float* __restrict__ bconv,
        const float* __restrict__ ln,
        const float* __restrict__ Wnext, const float* __restrict__ bnext,
        const int* __restrict__ batch, int is_last) {
    __shared__ float sw[784];
    bool has_next = (Wnext != nullptr);
    if (has_next) load_wproj(sw, Wnext, bnext);
    Slot s = make_slot();
    float w3[16];
    #pragma unroll
    for (int k = 0; k < 16; k++) w3[k] = W[3 * 256 + k * 16 + s.j];
    float b1 = bconv[16 + s.j];
    float gn = ln[s.j], bn = ln[16 + s.j];
    for (int i = s.slot; i < N_ATM; i += s.stride) {
        float2 nd = *(const float2*)(g_accG + (size_t)i * 32 + 2 * s.j);
        float xv = g_h_atm[(size_t)i * 16 + s.j];
        float u = b1 + nd.x / (nd.y + 1e-5f);
        #pragma unroll
        for (int k = 0; k < 16; k++)
            u += __shfl_sync(0xffffffffu, xv, s.grp | k) * w3[k];
        float xn = xv + siluf_(ln16(u, gn, bn));
        *(float2*)(g_accG + (size_t)i * 32 + 2 * s.j) = make_float2(0.0f, 0.0f);
        if (is_last) {
            atomicAdd(&g_pooled[batch[i] * 16 + s.j], xn);
        } else {
            g_h_atm[(size_t)i * 16 + s.j] = xn;
            proj_store(xn, s, sw, g_aps, g_apd, i);
        }
    }
}

// ---------------- head (also re-zeroes pooled for next replay) ----------------
__global__ void k_head(const float* __restrict__ fp,
                       const float* __restrict__ l1W, const float* __restrict__ l1b,
                       const float* __restrict__ l2W, const float* __restrict__ l2b,
                       float* __restrict__ out) {
    int g = threadIdx.x;  // one block of 256
    float p[16];
    #pragma unroll
    for (int i = 0; i < 16; i++) p[i] = g_pooled[g * 16 + i];
    float f0 = fp[2 * g], f1 = fp[2 * g + 1];
    float acc = l2b[0];
    #pragma unroll
    for (int jo = 0; jo < 16; jo++) {
        float h = l1b[jo];
        #pragma unroll
        for (int i = 0; i < 16; i++) h += p[i] * l1W[i * 16 + jo];
        h += f0 * l1W[16 * 16 + jo] + f1 * l1W[17 * 16 + jo];
        h = (h > 0.0f) ? h : 0.01f * h;
        acc += h * l2W[jo];
    }
    out[g] = acc;
    #pragma unroll
    for (int i = 0; i < 16; i++) g_pooled[g * 16 + i] = 0.0f;
}

// ---------------- launch ----------------
extern "C" void kernel_launch(void* const* d_in, const int* in_sizes, int n_in,
                              void* d_out, int out_size) {
    const int*   x_atm = (const int*)d_in[0];
    const float* x_bnd = (const float*)d_in[1];
    const float* x_ang = (const float*)d_in[2];
    const int*   mask  = (const int*)d_in[3];
    const int*   eG    = (const int*)d_in[4];
    const int*   eA    = (const int*)d_in[5];
    const int*   batch = (const int*)d_in[6];
    const float* fp    = (const float*)d_in[7];
    const float* W1    = (const float*)d_in[8];
    const float* b1    = (const float*)d_in[9];
    const float* W2    = (const float*)d_in[10];
    const float* b2    = (const float*)d_in[11];
    const float* lg    = (const float*)d_in[12];
    const float* lb    = (const float*)d_in[13];
    const float* cW    = (const float*)d_in[14];  // [3,2,5,16,16]
    const float* cb    = (const float*)d_in[15];  // [3,2,2,16]
    const float* cln   = (const float*)d_in[16];  // [3,2,2,2,16]
    const float* l1W   = (const float*)d_in[17];
    const float* l1b   = (const float*)d_in[18];
    const float* l2W   = (const float*)d_in[19];
    const float* l2b   = (const float*)d_in[20];
    float* out = (float*)d_out;

    #define WA(c)  (cW  + ((c) * 2 + 0) * 5 * 256)
    #define BA(c)  (cb  + ((c) * 2 + 0) * 32)
    #define LNA(c) (cln + ((c) * 2 + 0) * 64)
    #define WG(c)  (cW  + ((c) * 2 + 1) * 5 * 256)
    #define BG(c)  (cb  + ((c) * 2 + 1) * 32)
    #define LNG(c) (cln + ((c) * 2 + 1) * 64)

    k_enc_atm<<<512, 256>>>(x_atm, W1 + 0 * 256, b1 + 0 * 16, W2 + 0 * 256, b2 + 0 * 16,
                            lg + 0 * 16, lb + 0 * 16, WG(0), BG(0));
    k_enc_bnd<<<2048, 256>>>(x_bnd, W1 + 1 * 256, b1 + 1 * 16, W2 + 1 * 256, b2 + 1 * 16,
                             lg + 1 * 16, lb + 1 * 16, WA(0), BA(0));

    for (int c = 0; c < 3; c++) {
        if (c == 0) {
            k_edge_A_first<<<8192, 256>>>(eA, eA + N_ANG, x_ang, mask,
                                          W1, b1, W2, b2, lg, lb, WA(0), LNA(0));
        } else {
            k_edge_A<<<8192, 256>>>(eA, eA + N_ANG, WA(c), LNA(c), (c < 2) ? 1 : 0);
        }

        const float* WnA = (c < 2) ? WA(c + 1) : nullptr;
        const float* bnA = (c < 2) ? BA(c + 1) : nullptr;
        k_edge_G<<<8192, 256>>>(eG, eG + N_BND, WG(c), LNG(c),
                                WA(c), BA(c), LNA(c), WnA, bnA);

        const float* WnG = (c < 2) ? WG(c + 1) : nullptr;
        const float* bnG = (c < 2) ? BG(c + 1) : nullptr;
        k_node_G<<<512, 256>>>(WG(c), BG(c), LNG(c), WnG, bnG, batch, (c == 2) ? 1 : 0);
    }

    k_head<<<1, 256>>>(fp, l1W, l1b, l2W, l2b, out);
}

// round 6
// speedup vs baseline: 1.7600x; 1.0243x over previous
#include <cuda_runtime.h>
#include <cuda_fp16.h>

#define DIM 16
#define N_ATM 131072
#define N_BND 1048576
#define N_ANG 2097152
#define N_GRAPHS 256
#define PI_F 3.14159265358979323846f

// ---------------- scratch (device globals; zero-init; invariants restored each replay) ----
__device__ float    g_h_atm[N_ATM * DIM];
__device__ float    g_h_bnd[N_BND * DIM];
__device__ __half   g_h_ang[N_ANG * DIM];   // fp16 storage (post-LN, O(1) values)
__device__ unsigned g_accA[N_BND * DIM];    // half2(num,den) per (bond, channel); zeroed by edge_G
__device__ unsigned g_accG[N_ATM * DIM];    // half2(num,den) per (atom, channel); zeroed by node_G
__device__ unsigned g_bps[N_BND * DIM];     // bond src-proj half2(p0,p4)
__device__ __half   g_bpd[N_BND * DIM];     // bond dst-proj p1 (half)
__device__ unsigned g_aps[N_ATM * DIM];     // atom src-proj half2(p0,p4)
__device__ __half   g_apd[N_ATM * DIM];     // atom dst-proj p1 (half)
__device__ float    g_pooled[N_GRAPHS * DIM];

// ---------------- helpers ----------------
__device__ __forceinline__ float sigmoidf_(float x) { return 1.0f / (1.0f + __expf(-x)); }
__device__ __forceinline__ float siluf_(float x)    { return x / (1.0f + __expf(-x)); }

__device__ __forceinline__ float ln16(float x, float g, float b) {
    float s = x, q = x * x;
    #pragma unroll
    for (int off = 8; off; off >>= 1) {
        s += __shfl_xor_sync(0xffffffffu, s, off);
        q += __shfl_xor_sync(0xffffffffu, q, off);
    }
    float mu  = s * (1.0f / 16.0f);
    float var = q * (1.0f / 16.0f) - mu * mu;
    return (x - mu) * rsqrtf(var + 1e-5f) * g + b;
}

struct Slot { int j, grp, lane, slot, stride; };
__device__ __forceinline__ Slot make_slot() {
    Slot s;
    int t = blockIdx.x * blockDim.x + threadIdx.x;
    s.lane = t & 31;
    s.j = s.lane & 15;
    s.grp = s.lane & 16;
    s.slot = ((t >> 5) << 1) + (s.grp >> 4);
    s.stride = ((gridDim.x * blockDim.x) >> 5) << 1;
    return s;
}

// quad-packed fp16 reduction: 4 channels share one red.v4.f16x2 (16B)
__device__ __forceinline__ void red_quad(unsigned* base, int node, const Slot& s,
                                         float num, float den) {
    __half2 h = __floats2half2_rn(num, den);
    unsigned v = *reinterpret_cast<unsigned*>(&h);
    int b = s.lane & ~3;
    unsigned v0 = __shfl_sync(0xffffffffu, v, b);
    unsigned v1 = __shfl_sync(0xffffffffu, v, b | 1);
    unsigned v2 = __shfl_sync(0xffffffffu, v, b | 2);
    unsigned v3 = __shfl_sync(0xffffffffu, v, b | 3);
    if ((s.lane & 3) == 0) {
        unsigned* p = base + (size_t)node * 16 + s.j;
        asm volatile("red.global.add.noftz.v4.f16x2 [%0], {%1, %2, %3, %4};"
                     :: "l"(p), "r"(v0), "r"(v1), "r"(v2), "r"(v3) : "memory");
    }
}

// smem weight pack for fused projection: [0,256)=W0, [256,512)=W1, [512,768)=W4, [768,784)=b0
__device__ __forceinline__ void load_wproj(float* sw, const float* W, const float* b) {
    for (int i = threadIdx.x; i < 784; i += blockDim.x) {
        if (i < 768) {
            int m = i >> 8;
            int mm = (m == 2) ? 4 : m;
            sw[i] = W[mm * 256 + (i & 255)];
        } else {
            sw[i] = b[i - 768];
        }
    }
    __syncthreads();
}

// project register value v through smem weights; store fp16-packed node projections
__device__ __forceinline__ void proj_store(float v, const Slot& s, const float* sw,
                                           unsigned* dst_s, __half* dst_d, int i) {
    float p0 = sw[768 + s.j], p1 = 0.0f, p4 = 0.0f;
    #pragma unroll
    for (int k = 0; k < 16; k++) {
        float a = __shfl_sync(0xffffffffu, v, s.grp | k);
        p0 += a * sw[k * 16 + s.j];
        p1 += a * sw[256 + k * 16 + s.j];
        p4 += a * sw[512 + k * 16 + s.j];
    }
    __half2 h = __floats2half2_rn(p0, p4);
    dst_s[(size_t)i * 16 + s.j] = *reinterpret_cast<unsigned*>(&h);
    dst_d[(size_t)i * 16 + s.j] = __float2half_rn(p1);
}

// shared edge-A body once ev (angle feature) is known
__device__ __forceinline__ void edgeA_core(int ed, int si, int di, float ev,
                                           const float* w2c, float ge, float be,
                                           const Slot& s, bool write_e) {
    unsigned pu = g_bps[(size_t)si * 16 + s.j];
    __half2 ph = *reinterpret_cast<__half2*>(&pu);
    float p0 = __low2float(ph), p4 = __high2float(ph);
    float p1 = __half2float(g_bpd[(size_t)di * 16 + s.j]);
    float z = p0 + p1;
    #pragma unroll
    for (int k = 0; k < 16; k++)
        z += __shfl_sync(0xffffffffu, ev, s.grp | k) * w2c[k];
    float sig = sigmoidf_(z);
    red_quad(g_accA, di, s, sig * p4, sig);
    if (write_e)
        g_h_ang[(size_t)ed * 16 + s.j] = __float2half_rn(ev + siluf_(ln16(z, ge, be)));
}

// ---------------- encoders (fused with first-conv projections) ----------------
__global__ void __launch_bounds__(256) k_enc_atm(
        const int* __restrict__ xatm,
        const float* __restrict__ W1, const float* __restrict__ b1,
        const float* __restrict__ W2, const float* __restrict__ b2,
        const float* __restrict__ lg, const float* __restrict__ lb,
        const float* __restrict__ Wg0, const float* __restrict__ bg0) {
    __shared__ float sw[784];
    load_wproj(sw, Wg0, bg0);
    Slot s = make_slot();
    float w2c[16];
    #pragma unroll
    for (int k = 0; k < 16; k++) w2c[k] = W2[k * 16 + s.j];
    float b1j = b1[s.j], b2j = b2[s.j], gj = lg[s.j], bj = lb[s.j];
    for (int a = s.slot; a < N_ATM; a += s.stride) {
        int sp = xatm[a];
        float h = siluf_(W1[sp * 16 + s.j] + b1j);
        float z = b2j;
        #pragma unroll
        for (int k = 0; k < 16; k++)
            z += __shfl_sync(0xffffffffu, h, s.grp | k) * w2c[k];
        float v = ln16(z, gj, bj);
        g_h_atm[a * 16 + s.j] = v;
        proj_store(v, s, sw, g_aps, g_apd, a);
    }
}

__global__ void __launch_bounds__(256) k_enc_bnd(
        const float* __restrict__ xb,
        const float* __restrict__ W1, const float* __restrict__ b1,
        const float* __restrict__ W2, const float* __restrict__ b2,
        const float* __restrict__ lg, const float* __restrict__ lb,
        const float* __restrict__ Wa0, const float* __restrict__ ba0) {
    __shared__ float sw[784];
    load_wproj(sw, Wa0, ba0);
    Slot s = make_slot();
    float w1c[16], w2c[16];
    #pragma unroll
    for (int k = 0; k < 16; k++) { w1c[k] = W1[k * 16 + s.j]; w2c[k] = W2[k * 16 + s.j]; }
    float b1j = b1[s.j], b2j = b2[s.j], gj = lg[s.j], bj = lb[s.j];
    const float nrm = sqrtf(2.0f / 5.0f);
    for (int e = s.slot; e < N_BND; e += s.stride) {
        float xx = xb[e] + 1e-5f;
        float f = nrm * sinf((float)(s.j + 1) * PI_F * xx * (1.0f / 5.0f)) / xx;
        float h = b1j;
        #pragma unroll
        for (int k = 0; k < 16; k++)
            h += __shfl_sync(0xffffffffu, f, s.grp | k) * w1c[k];
        h = siluf_(h);
        float z = b2j;
        #pragma unroll
        for (int k = 0; k < 16; k++)
            z += __shfl_sync(0xffffffffu, h, s.grp | k) * w2c[k];
        float v = ln16(z, gj, bj);
        g_h_bnd[e * 16 + s.j] = v;
        proj_store(v, s, sw, g_bps, g_bpd, e);
    }
}

// ---------------- A-graph edge phase, conv 0: fused angle encoder ----------------
__global__ void __launch_bounds__(256) k_edge_A_first(
        const int* __restrict__ src, const int* __restrict__ dst,
        const float* __restrict__ xang, const int* __restrict__ mask,
        const float* __restrict__ W1, const float* __restrict__ b1,
        const float* __restrict__ W2, const float* __restrict__ b2,
        const float* __restrict__ lg, const float* __restrict__ lb,
        const float* __restrict__ W, const float* __restrict__ ln) {
    __shared__ float sw[1152];
    for (int i = threadIdx.x; i < 1152; i += blockDim.x) {
        if (i < 512)       sw[i] = W1[512 + i];           // sets 2,3 of W1
        else if (i < 1024) sw[i] = W2[i];                 // sets 2,3 of W2
        else {
            int idx = i - 1024, gsel = idx >> 4, j = idx & 15;
            const float* tbl[8] = { b1 + 32, b1 + 48, b2 + 32, b2 + 48,
                                    lg + 32, lg + 48, lb + 32, lb + 48 };
            sw[i] = tbl[gsel][j];
        }
    }
    __syncthreads();
    Slot s = make_slot();
    float w2c[16];
    #pragma unroll
    for (int k = 0; k < 16; k++) w2c[k] = W[2 * 256 + k * 16 + s.j];
    float ge = ln[32 + s.j], be = ln[48 + s.j];
    const float cb = (float)s.j * (PI_F / 15.0f);
    const float cd = -PI_F + (float)s.j * (2.0f * PI_F / 15.0f);
    const float* sv = sw + 1024;
    for (int ed = s.slot; ed < N_ANG; ed += s.stride) {
        int si = src[ed], di = dst[ed];
        float x = xang[ed];
        bool m = mask[ed] != 0;
        int o = m ? 256 : 0, o16 = m ? 16 : 0;
        float gam = m ? (7.5f / PI_F) : (15.0f / PI_F);
        float t = gam * (x - (m ? cd : cb));
        float f = __expf(-t * t);
        const float* w1p = sw + o;
        const float* w2p = sw + 512 + o;
        float h = sv[o16 + s.j];
        #pragma unroll
        for (int k = 0; k < 16; k++)
            h += __shfl_sync(0xffffffffu, f, s.grp | k) * w1p[k * 16 + s.j];
        h = siluf_(h);
        float z2 = sv[32 + o16 + s.j];
        #pragma unroll
        for (int k = 0; k < 16; k++)
            z2 += __shfl_sync(0xffffffffu, h, s.grp | k) * w2p[k * 16 + s.j];
        float ev = ln16(z2, sv[64 + o16 + s.j], sv[96 + o16 + s.j]);
        edgeA_core(ed, si, di, ev, w2c, ge, be, s, true);
    }
}

// ---------------- A-graph edge phase, conv 1/2 ----------------
__global__ void __launch_bounds__(256) k_edge_A(
        const int* __restrict__ src, const int* __restrict__ dst,
        const float* __restrict__ W, const float* __restrict__ ln, int write_e) {
    Slot s = make_slot();
    float w2c[16];
    #pragma unroll
    for (int k = 0; k < 16; k++) w2c[k] = W[2 * 256 + k * 16 + s.j];
    float ge = ln[32 + s.j], be = ln[48 + s.j];
    for (int ed = s.slot; ed < N_ANG; ed += s.stride) {
        int si = src[ed], di = dst[ed];
        float ev = __half2float(g_h_ang[(size_t)ed * 16 + s.j]);
        edgeA_core(ed, si, di, ev, w2c, ge, be, s, write_e != 0);
    }
}

// ---------------- G-graph edge phase with FUSED A-node update ----------------
// smem: [0,784) next-A proj pack; [784,1040) W3_A; [1040,1056) b1_A;
//       [1056,1072) gn_A; [1072,1088) bn_A
__global__ void __launch_bounds__(256) k_edge_G(
        const int* __restrict__ src, const int* __restrict__ dst,
        const float* __restrict__ Wg, const float* __restrict__ lnG,
        const float* __restrict__ Wa, const float* __restrict__ ba,
        const float* __restrict__ lnA,
        const float* __restrict__ Wnext, const float* __restrict__ bnext) {
    __shared__ float sw[1088];
    bool has_next = (Wnext != nullptr);
    for (int i = threadIdx.x; i < 1088; i += blockDim.x) {
        if (i < 784) {
            if (has_next) {
                if (i < 768) {
                    int m = i >> 8;
                    int mm = (m == 2) ? 4 : m;
                    sw[i] = Wnext[mm * 256 + (i & 255)];
                } else sw[i] = bnext[i - 768];
            }
        }
        else if (i < 1040) sw[i] = Wa[3 * 256 + (i - 784)];
        else if (i < 1056) sw[i] = ba[16 + (i - 1040)];
        else if (i < 1072) sw[i] = lnA[i - 1056];
        else               sw[i] = lnA[16 + (i - 1072)];
    }
    __syncthreads();
    Slot s = make_slot();
    float w2c[16];
    #pragma unroll
    for (int k = 0; k < 16; k++) w2c[k] = Wg[2 * 256 + k * 16 + s.j];
    float ge = lnG[32 + s.j], be = lnG[48 + s.j];
    float b1A = sw[1040 + s.j], gnA = sw[1056 + s.j], bnA = sw[1072 + s.j];
    for (int ed = s.slot; ed < N_BND; ed += s.stride) {
        int si = src[ed], di = dst[ed];
        // --- fused A-node update for bond ed ---
        unsigned au = g_accA[(size_t)ed * 16 + s.j];
        __half2 ah = *reinterpret_cast<__half2*>(&au);
        float xv = g_h_bnd[(size_t)ed * 16 + s.j];
        float u = b1A + __low2float(ah) / (__high2float(ah) + 1e-5f);
        #pragma unroll
        for (int k = 0; k < 16; k++)
            u += __shfl_sync(0xffffffffu, xv, s.grp | k) * sw[784 + k * 16 + s.j];
        float ev = xv + siluf_(ln16(u, gnA, bnA));
        g_accA[(size_t)ed * 16 + s.j] = 0u;
        // --- G edge ---
        unsigned pu = g_aps[(size_t)si * 16 + s.j];
        __half2 ph = *reinterpret_cast<__half2*>(&pu);
        float p0 = __low2float(ph), p4 = __high2float(ph);
        float p1 = __half2float(g_apd[(size_t)di * 16 + s.j]);
        float z = p0 + p1;
        #pragma unroll
        for (int k = 0; k < 16; k++)
            z += __shfl_sync(0xffffffffu, ev, s.grp | k) * w2c[k];
        float sig = sigmoidf_(z);
        red_quad(g_accG, di, s, sig * p4, sig);
        if (has_next) {
            float en = ev + siluf_(ln16(z, ge, be));
            g_h_bnd[(size_t)ed * 16 + s.j] = en;
            proj_store(en, s, sw, g_bps, g_bpd, ed);
        }
    }
}

// ---------------- G-graph node phase (update atoms; zero accG; next-G proj; pool) ----
__global__ void __launch_bounds__(256) k_node_G(
        const float* __restrict__ W, const float* __restrict__ bconv,
        const float* __restrict__ ln,
        const float* __restrict__ Wnext, const float* __restrict__ bnext,
        const int* __restrict__ batch, int is_last) {
    __shared__ float sw[784];
    bool has_next = (Wnext != nullptr);
    if (has_next) load_wproj(sw, Wnext, bnext);
    Slot s = make_slot();
    float w3[16];
    #pragma unroll
    for (int k = 0; k < 16; k++) w3[k] = W[3 * 256 + k * 16 + s.j];
    float b1 = bconv[16 + s.j];
    float gn = ln[s.j], bn = ln[16 + s.j];
    for (int i = s.slot; i < N_ATM; i += s.stride) {
        unsigned au = g_accG[(size_t)i * 16 + s.j];
        __half2 ah = *reinterpret_cast<__half2*>(&au);
        float xv = g_h_atm[(size_t)i * 16 + s.j];
        float u = b1 + __low2float(ah) / (__high2float(ah) + 1e-5f);
        #pragma unroll
        for (int k = 0; k < 16; k++)
            u += __shfl_sync(0xffffffffu, xv, s.grp | k) * w3[k];
        float xn = xv + siluf_(ln16(u, gn, bn));
        g_accG[(size_t)i * 16 + s.j] = 0u;
        if (is_last) {
            atomicAdd(&g_pooled[batch[i] * 16 + s.j], xn);
        } else {
            g_h_atm[(size_t)i * 16 + s.j] = xn;
            proj_store(xn, s, sw, g_aps, g_apd, i);
        }
    }
}

// ---------------- head (also re-zeroes pooled for next replay) ----------------
__global__ void k_head(const float* __restrict__ fp,
                       const float* __restrict__ l1W, const float* __restrict__ l1b,
                       const float* __restrict__ l2W, const float* __restrict__ l2b,
                       float* __restrict__ out) {
    int g = threadIdx.x;  // one block of 256
    float p[16];
    #pragma unroll
    for (int i = 0; i < 16; i++) p[i] = g_pooled[g * 16 + i];
    float f0 = fp[2 * g], f1 = fp[2 * g + 1];
    float acc = l2b[0];
    #pragma unroll
    for (int jo = 0; jo < 16; jo++) {
        float h = l1b[jo];
        #pragma unroll
        for (int i = 0; i < 16; i++) h += p[i] * l1W[i * 16 + jo];
        h += f0 * l1W[16 * 16 + jo] + f1 * l1W[17 * 16 + jo];
        h = (h > 0.0f) ? h : 0.01f * h;
        acc += h * l2W[jo];
    }
    out[g] = acc;
    #pragma unroll
    for (int i = 0; i < 16; i++) g_pooled[g * 16 + i] = 0.0f;
}

// ---------------- launch ----------------
extern "C" void kernel_launch(void* const* d_in, const int* in_sizes, int n_in,
                              void* d_out, int out_size) {
    const int*   x_atm = (const int*)d_in[0];
    const float* x_bnd = (const float*)d_in[1];
    const float* x_ang = (const float*)d_in[2];
    const int*   mask  = (const int*)d_in[3];
    const int*   eG    = (const int*)d_in[4];
    const int*   eA    = (const int*)d_in[5];
    const int*   batch = (const int*)d_in[6];
    const float* fp    = (const float*)d_in[7];
    const float* W1    = (const float*)d_in[8];
    const float* b1    = (const float*)d_in[9];
    const float* W2    = (const float*)d_in[10];
    const float* b2    = (const float*)d_in[11];
    const float* lg    = (const float*)d_in[12];
    const float* lb    = (const float*)d_in[13];
    const float* cW    = (const float*)d_in[14];  // [3,2,5,16,16]
    const float* cb    = (const float*)d_in[15];  // [3,2,2,16]
    const float* cln   = (const float*)d_in[16];  // [3,2,2,2,16]
    const float* l1W   = (const float*)d_in[17];
    const float* l1b   = (const float*)d_in[18];
    const float* l2W   = (const float*)d_in[19];
    const float* l2b   = (const float*)d_in[20];
    float* out = (float*)d_out;

    #define WA(c)  (cW  + ((c) * 2 + 0) * 5 * 256)
    #define BA(c)  (cb  + ((c) * 2 + 0) * 32)
    #define LNA(c) (cln + ((c) * 2 + 0) * 64)
    #define WG(c)  (cW  + ((c) * 2 + 1) * 5 * 256)
    #define BG(c)  (cb  + ((c) * 2 + 1) * 32)
    #define LNG(c) (cln + ((c) * 2 + 1) * 64)

    k_enc_atm<<<512, 256>>>(x_atm, W1 + 0 * 256, b1 + 0 * 16, W2 + 0 * 256, b2 + 0 * 16,
                            lg + 0 * 16, lb + 0 * 16, WG(0), BG(0));
    k_enc_bnd<<<2048, 256>>>(x_bnd, W1 + 1 * 256, b1 + 1 * 16, W2 + 1 * 256, b2 + 1 * 16,
                             lg + 1 * 16, lb + 1 * 16, WA(0), BA(0));

    for (int c = 0; c < 3; c++) {
        if (c == 0) {
            k_edge_A_first<<<8192, 256>>>(eA, eA + N_ANG, x_ang, mask,
                                          W1, b1, W2, b2, lg, lb, WA(0), LNA(0));
        } else {
            k_edge_A<<<8192, 256>>>(eA, eA + N_ANG, WA(c), LNA(c), (c < 2) ? 1 : 0);
        }

        const float* WnA = (c < 2) ? WA(c + 1) : nullptr;
        const float* bnA = (c < 2) ? BA(c + 1) : nullptr;
        k_edge_G<<<8192, 256>>>(eG, eG + N_BND, WG(c), LNG(c),
                                WA(c), BA(c), LNA(c), WnA, bnA);

        const float* WnG = (c < 2) ? WG(c + 1) : nullptr;
        const float* bnG = (c < 2) ? BG(c + 1) : nullptr;
        k_node_G<<<512, 256>>>(WG(c), BG(c), LNG(c), WnG, bnG, batch, (c == 2) ? 1 : 0);
    }

    k_head<<<1, 256>>>(fp, l1W, l1b, l2W, l2b, out);
}